// round 1
// baseline (speedup 1.0000x reference)
#include <cuda_runtime.h>
#include <math.h>

#define SQ 2048
#define EM 1024
#define DM 64
#define NH 16

// ---------------- scratch (device globals; no allocation allowed) ----------------
__device__ __align__(16) float g_K[SQ * DM];
__device__ __align__(16) float g_Q[SQ * DM];
__device__ __align__(16) float g_V[SQ * DM];
__device__ __align__(16) float g_Kh[NH * SQ * DM];
__device__ __align__(16) float g_Qh[NH * SQ * DM];
__device__ __align__(16) float g_Vh[NH * SQ * DM];
__device__ __align__(16) float g_cat[SQ * EM];
__device__ __align__(16) float g_out[SQ * EM];

// ---------------- shared tiled SGEMM: C[M,N] = A[M,K] @ B[N,K]^T (+bias) ----------
// 64x64 block tile, BK=16, 256 threads, 4x4 register micro-tile per thread.
__device__ __forceinline__ void gemm64(const float* __restrict__ A, int lda,
                                       const float* __restrict__ B, int ldb,
                                       const float* __restrict__ bias,
                                       float* __restrict__ C, int ldc,
                                       int Kd, int m0, int n0)
{
    __shared__ float As[16][68];
    __shared__ float Bs[16][68];
    const int tid = threadIdx.x;
    const int tx  = tid & 15;
    const int ty  = tid >> 4;
    const int lr  = tid >> 2;          // load row 0..63
    const int lc  = (tid & 3) << 2;    // load k-offset 0,4,8,12

    float acc[4][4];
#pragma unroll
    for (int i = 0; i < 4; i++)
#pragma unroll
        for (int j = 0; j < 4; j++) acc[i][j] = 0.f;

    const float* Ap = A + (size_t)(m0 + lr) * lda + lc;
    const float* Bp = B + (size_t)(n0 + lr) * ldb + lc;

    for (int k0 = 0; k0 < Kd; k0 += 16) {
        float4 a4 = *reinterpret_cast<const float4*>(Ap + k0);
        float4 b4 = *reinterpret_cast<const float4*>(Bp + k0);
        __syncthreads();
        As[lc + 0][lr] = a4.x; As[lc + 1][lr] = a4.y;
        As[lc + 2][lr] = a4.z; As[lc + 3][lr] = a4.w;
        Bs[lc + 0][lr] = b4.x; Bs[lc + 1][lr] = b4.y;
        Bs[lc + 2][lr] = b4.z; Bs[lc + 3][lr] = b4.w;
        __syncthreads();
#pragma unroll
        for (int k = 0; k < 16; k++) {
            float a0 = As[k][ty * 4 + 0], a1 = As[k][ty * 4 + 1];
            float a2 = As[k][ty * 4 + 2], a3 = As[k][ty * 4 + 3];
            float b0 = Bs[k][tx * 4 + 0], b1 = Bs[k][tx * 4 + 1];
            float b2 = Bs[k][tx * 4 + 2], b3 = Bs[k][tx * 4 + 3];
            acc[0][0] += a0 * b0; acc[0][1] += a0 * b1; acc[0][2] += a0 * b2; acc[0][3] += a0 * b3;
            acc[1][0] += a1 * b0; acc[1][1] += a1 * b1; acc[1][2] += a1 * b2; acc[1][3] += a1 * b3;
            acc[2][0] += a2 * b0; acc[2][1] += a2 * b1; acc[2][2] += a2 * b2; acc[2][3] += a2 * b3;
            acc[3][0] += a3 * b0; acc[3][1] += a3 * b1; acc[3][2] += a3 * b2; acc[3][3] += a3 * b3;
        }
    }

#pragma unroll
    for (int i = 0; i < 4; i++) {
        const int m = m0 + ty * 4 + i;
#pragma unroll
        for (int j = 0; j < 4; j++) {
            const int n = n0 + tx * 4 + j;
            float v = acc[i][j];
            if (bias) v += bias[n];
            C[(size_t)m * ldc + n] = v;
        }
    }
}

// ---------------- kernel 1: shared K/Q/V projections  [S,E]@[E,D]^T ----------------
__global__ __launch_bounds__(256) void k_proj(const float* __restrict__ x,
                                              const float* __restrict__ Wk,
                                              const float* __restrict__ Wq,
                                              const float* __restrict__ Wv)
{
    const float* W;
    float* C;
    if (blockIdx.z == 0)      { W = Wk; C = g_K; }
    else if (blockIdx.z == 1) { W = Wq; C = g_Q; }
    else                      { W = Wv; C = g_V; }
    gemm64(x, EM, W, EM, nullptr, C, DM, EM, blockIdx.y * 64, 0);
}

// ---------------- kernel 2: per-head linears, batched over (type, head) -----------
__global__ __launch_bounds__(256) void k_headlin(const float* __restrict__ hWk,
                                                 const float* __restrict__ hbk,
                                                 const float* __restrict__ hWv,
                                                 const float* __restrict__ hbv,
                                                 const float* __restrict__ hWq,
                                                 const float* __restrict__ hbq)
{
    const int z = blockIdx.z;
    const int t = z >> 4;     // 0: K, 1: V, 2: Q
    const int h = z & 15;
    const float *A, *B, *bias;
    float* C;
    if (t == 0)      { A = g_K; B = hWk + h * DM * DM; bias = hbk + h * DM; C = g_Kh + (size_t)h * SQ * DM; }
    else if (t == 1) { A = g_V; B = hWv + h * DM * DM; bias = hbv + h * DM; C = g_Vh + (size_t)h * SQ * DM; }
    else             { A = g_Q; B = hWq + h * DM * DM; bias = hbq + h * DM; C = g_Qh + (size_t)h * SQ * DM; }
    gemm64(A, DM, B, DM, bias, C, DM, DM, blockIdx.y * 64, 0);
}

// ---------------- kernel 3: flash attention (fp32, online softmax) -----------------
// grid (SQ/128, NH), 128 threads; thread owns one full query row.
__global__ __launch_bounds__(128) void k_attn()
{
    const int h   = blockIdx.y;
    const int row = blockIdx.x * 128 + threadIdx.x;
    const float* Qb = g_Qh + (size_t)h * SQ * DM;
    const float* Kb = g_Kh + (size_t)h * SQ * DM;
    const float* Vb = g_Vh + (size_t)h * SQ * DM;

    __shared__ float Ks[32][64];
    __shared__ float Vs[32][64];

    float q[64], o[64];
#pragma unroll
    for (int d = 0; d < 64; d += 4) {
        float4 v = *reinterpret_cast<const float4*>(Qb + (size_t)row * 64 + d);
        q[d] = v.x * 0.125f; q[d + 1] = v.y * 0.125f;   // fold 1/sqrt(64) into q
        q[d + 2] = v.z * 0.125f; q[d + 3] = v.w * 0.125f;
        o[d] = 0.f; o[d + 1] = 0.f; o[d + 2] = 0.f; o[d + 3] = 0.f;
    }
    float m = -1e30f, l = 0.f;

    for (int t0 = 0; t0 < SQ; t0 += 32) {
        __syncthreads();
#pragma unroll
        for (int r = 0; r < 4; r++) {
            int f  = threadIdx.x + r * 128;   // float4 index 0..511
            int j  = f >> 4;
            int dd = (f & 15) << 2;
            *reinterpret_cast<float4*>(&Ks[j][dd]) =
                *reinterpret_cast<const float4*>(Kb + (size_t)(t0 + j) * 64 + dd);
            *reinterpret_cast<float4*>(&Vs[j][dd]) =
                *reinterpret_cast<const float4*>(Vb + (size_t)(t0 + j) * 64 + dd);
        }
        __syncthreads();

        float s[32];
#pragma unroll 4
        for (int j = 0; j < 32; j++) {
            float a0 = 0.f, a1 = 0.f, a2 = 0.f, a3 = 0.f;
#pragma unroll
            for (int d = 0; d < 64; d += 4) {
                float4 k4 = *reinterpret_cast<const float4*>(&Ks[j][d]);  // smem broadcast
                a0 += q[d] * k4.x;     a1 += q[d + 1] * k4.y;
                a2 += q[d + 2] * k4.z; a3 += q[d + 3] * k4.w;
            }
            s[j] = (a0 + a1) + (a2 + a3);
        }

        float tmax = m;
#pragma unroll
        for (int j = 0; j < 32; j++) tmax = fmaxf(tmax, s[j]);
        const float corr = __expf(m - tmax);
        m = tmax;
        l *= corr;
#pragma unroll
        for (int d = 0; d < 64; d++) o[d] *= corr;
#pragma unroll
        for (int j = 0; j < 32; j++) { float p = __expf(s[j] - m); l += p; s[j] = p; }

#pragma unroll 4
        for (int j = 0; j < 32; j++) {
            const float p = s[j];
#pragma unroll
            for (int d = 0; d < 64; d += 4) {
                float4 v4 = *reinterpret_cast<const float4*>(&Vs[j][d]);  // smem broadcast
                o[d] += p * v4.x;     o[d + 1] += p * v4.y;
                o[d + 2] += p * v4.z; o[d + 3] += p * v4.w;
            }
        }
    }

    const float inv = 1.f / l;
    float* dst = g_cat + (size_t)row * EM + h * DM;
#pragma unroll
    for (int d = 0; d < 64; d += 4) {
        float4 v;
        v.x = o[d] * inv; v.y = o[d + 1] * inv;
        v.z = o[d + 2] * inv; v.w = o[d + 3] * inv;
        *reinterpret_cast<float4*>(dst + d) = v;
    }
}

// ---------------- kernel 4: out-proj [S,E]@[E,E]^T + bias -------------------------
__global__ __launch_bounds__(256) void k_outproj(const float* __restrict__ Wo,
                                                 const float* __restrict__ bo)
{
    gemm64(g_cat, EM, Wo, EM, bo, g_out, EM, EM, blockIdx.y * 64, blockIdx.x * 64);
}

// ---------------- kernel 5: residual + LayerNorm ----------------------------------
__device__ __forceinline__ float block_sum_256(float val, float* sh)
{
    const int lane = threadIdx.x & 31;
    const int w    = threadIdx.x >> 5;
#pragma unroll
    for (int o = 16; o > 0; o >>= 1) val += __shfl_xor_sync(0xffffffffu, val, o);
    if (lane == 0) sh[w] = val;
    __syncthreads();
    if (w == 0) {
        float t = (lane < 8) ? sh[lane] : 0.f;
#pragma unroll
        for (int o = 4; o > 0; o >>= 1) t += __shfl_xor_sync(0xffffffffu, t, o);
        if (lane == 0) sh[0] = t;
    }
    __syncthreads();
    const float r = sh[0];
    __syncthreads();
    return r;
}

__global__ __launch_bounds__(256) void k_ln(const float* __restrict__ x,
                                            const float* __restrict__ gamma,
                                            const float* __restrict__ beta,
                                            float* __restrict__ out)
{
    __shared__ float sh[8];
    const int srow = blockIdx.x;
    const float* orow = g_out + (size_t)srow * EM;
    const float* xrow = x + (size_t)srow * EM;

    float v[4];
    float sum = 0.f;
#pragma unroll
    for (int i = 0; i < 4; i++) {
        const int c = threadIdx.x + i * 256;
        v[i] = orow[c] + xrow[c];
        sum += v[i];
    }
    const float mean = block_sum_256(sum, sh) * (1.f / EM);

    float var = 0.f;
#pragma unroll
    for (int i = 0; i < 4; i++) {
        const float d = v[i] - mean;
        var += d * d;
    }
    const float rstd = rsqrtf(block_sum_256(var, sh) * (1.f / EM) + 1e-5f);

#pragma unroll
    for (int i = 0; i < 4; i++) {
        const int c = threadIdx.x + i * 256;
        out[(size_t)srow * EM + c] = (v[i] - mean) * rstd * gamma[c] + beta[c];
    }
}

// ---------------- launch ----------------------------------------------------------
extern "C" void kernel_launch(void* const* d_in, const int* in_sizes, int n_in,
                              void* d_out, int out_size)
{
    const float* x     = (const float*)d_in[0];
    const float* Wk    = (const float*)d_in[1];
    const float* Wq    = (const float*)d_in[2];
    const float* Wv    = (const float*)d_in[3];
    const float* hWk   = (const float*)d_in[4];
    const float* hbk   = (const float*)d_in[5];
    const float* hWv   = (const float*)d_in[6];
    const float* hbv   = (const float*)d_in[7];
    const float* hWq   = (const float*)d_in[8];
    const float* hbq   = (const float*)d_in[9];
    const float* Wo    = (const float*)d_in[10];
    const float* bo    = (const float*)d_in[11];
    const float* gamma = (const float*)d_in[12];
    const float* beta  = (const float*)d_in[13];
    float* out = (float*)d_out;

    k_proj<<<dim3(1, SQ / 64, 3), 256>>>(x, Wk, Wq, Wv);
    k_headlin<<<dim3(1, SQ / 64, 48), 256>>>(hWk, hbk, hWv, hbv, hWq, hbq);
    k_attn<<<dim3(SQ / 128, NH), 128>>>();
    k_outproj<<<dim3(EM / 64, SQ / 64), 256>>>(Wo, bo);
    k_ln<<<SQ, 256>>>(x, gamma, beta, out);
}

// round 2
// speedup vs baseline: 1.3953x; 1.3953x over previous
#include <cuda_runtime.h>
#include <math.h>

#define SQ 2048
#define EM 1024
#define DM 64
#define NH 16

// ---------------- scratch ----------------
__device__ __align__(16) float g_K[SQ * DM];
__device__ __align__(16) float g_Q[SQ * DM];
__device__ __align__(16) float g_V[SQ * DM];
__device__ __align__(16) float g_Kh[NH * SQ * DM];
__device__ __align__(16) float g_Qh[NH * SQ * DM];
__device__ __align__(16) float g_Vh[NH * SQ * DM];
__device__ __align__(16) float g_Vt[NH * SQ * DM];   // [h][d][s]
__device__ __align__(16) float g_cat[SQ * EM];
__device__ __align__(16) float g_out[SQ * EM];

// ---------------- tf32 helpers ----------------
__device__ __forceinline__ unsigned f2tf(float f) {
    unsigned u;
    asm("cvt.rna.tf32.f32 %0, %1;" : "=r"(u) : "f"(f));
    return u;
}

__device__ __forceinline__ void mma_tf32(float* d, const unsigned* a, const unsigned* b) {
    asm volatile(
        "mma.sync.aligned.m16n8k8.row.col.f32.tf32.tf32.f32 "
        "{%0,%1,%2,%3},{%4,%5,%6,%7},{%8,%9},{%0,%1,%2,%3};"
        : "+f"(d[0]), "+f"(d[1]), "+f"(d[2]), "+f"(d[3])
        : "r"(a[0]), "r"(a[1]), "r"(a[2]), "r"(a[3]), "r"(b[0]), "r"(b[1]));
}

// ---------------- unified tf32 GEMM: C[.,.] = A @ B^T (+bias) --------------------
// Block tile: 128 x BN, BK=32. Warps: 4 (m) x (BN/64) (n); warp tile 32 x 64.
template <int BN>
__device__ __forceinline__ void gemm_tc(const float* __restrict__ A, int lda,
                                        const float* __restrict__ B, int ldb,
                                        const float* __restrict__ bias,
                                        float* __restrict__ C, int ldc,
                                        int Kd, int m0, int n0,
                                        float (*As)[36], float (*Bs)[36])
{
    constexpr int NT = 2 * BN;           // threads: 128 or 256
    const int tid  = threadIdx.x;
    const int lane = tid & 31;
    const int warp = tid >> 5;
    const int wm   = warp & 3;
    const int wn   = warp >> 2;
    const int g    = lane >> 2;          // group id (row within frag)
    const int lam  = lane & 3;           // thread in group

    float acc[2][8][4];
#pragma unroll
    for (int mf = 0; mf < 2; mf++)
#pragma unroll
        for (int nf = 0; nf < 8; nf++)
#pragma unroll
            for (int i = 0; i < 4; i++) acc[mf][nf][i] = 0.f;

    for (int k0 = 0; k0 < Kd; k0 += 32) {
        // fill A tile 128x32 (scalar, coalesced, conflict-free STS)
#pragma unroll
        for (int e = tid; e < 128 * 32; e += NT) {
            int r = e >> 5, c = e & 31;
            As[r][c] = A[(size_t)(m0 + r) * lda + k0 + c];
        }
        // fill B tile BNx32
#pragma unroll
        for (int e = tid; e < BN * 32; e += NT) {
            int r = e >> 5, c = e & 31;
            Bs[r][c] = B[(size_t)(n0 + r) * ldb + k0 + c];
        }
        __syncthreads();

#pragma unroll
        for (int kf = 0; kf < 4; kf++) {
            unsigned a[2][4];
#pragma unroll
            for (int mf = 0; mf < 2; mf++) {
                int r = wm * 32 + mf * 16 + g;
                a[mf][0] = f2tf(As[r][kf * 8 + lam]);
                a[mf][1] = f2tf(As[r + 8][kf * 8 + lam]);
                a[mf][2] = f2tf(As[r][kf * 8 + lam + 4]);
                a[mf][3] = f2tf(As[r + 8][kf * 8 + lam + 4]);
            }
#pragma unroll
            for (int nf = 0; nf < 8; nf++) {
                unsigned b[2];
                int rb = wn * 64 + nf * 8 + g;
                b[0] = f2tf(Bs[rb][kf * 8 + lam]);
                b[1] = f2tf(Bs[rb][kf * 8 + lam + 4]);
                mma_tf32(acc[0][nf], a[0], b);
                mma_tf32(acc[1][nf], a[1], b);
            }
        }
        __syncthreads();
    }

    // epilogue
#pragma unroll
    for (int mf = 0; mf < 2; mf++) {
        const int row = m0 + wm * 32 + mf * 16 + g;
#pragma unroll
        for (int nf = 0; nf < 8; nf++) {
            const int col = n0 + wn * 64 + nf * 8 + 2 * lam;
            float b0 = bias ? bias[col] : 0.f;
            float b1 = bias ? bias[col + 1] : 0.f;
            float2 v0 = make_float2(acc[mf][nf][0] + b0, acc[mf][nf][1] + b1);
            float2 v1 = make_float2(acc[mf][nf][2] + b0, acc[mf][nf][3] + b1);
            *reinterpret_cast<float2*>(C + (size_t)row * ldc + col) = v0;
            *reinterpret_cast<float2*>(C + (size_t)(row + 8) * ldc + col) = v1;
        }
    }
}

// ---------------- kernel 1: shared K/Q/V projections ----------------
__global__ __launch_bounds__(128) void k_proj(const float* __restrict__ x,
                                              const float* __restrict__ Wk,
                                              const float* __restrict__ Wq,
                                              const float* __restrict__ Wv)
{
    __shared__ float As[128][36];
    __shared__ float Bs[64][36];
    const float* W;
    float* C;
    if (blockIdx.z == 0)      { W = Wk; C = g_K; }
    else if (blockIdx.z == 1) { W = Wq; C = g_Q; }
    else                      { W = Wv; C = g_V; }
    gemm_tc<64>(x, EM, W, EM, nullptr, C, DM, EM, blockIdx.y * 128, 0, As, Bs);
}

// ---------------- kernel 2: per-head linears ----------------
__global__ __launch_bounds__(128) void k_headlin(const float* __restrict__ hWk,
                                                 const float* __restrict__ hbk,
                                                 const float* __restrict__ hWv,
                                                 const float* __restrict__ hbv,
                                                 const float* __restrict__ hWq,
                                                 const float* __restrict__ hbq)
{
    __shared__ float As[128][36];
    __shared__ float Bs[64][36];
    const int z = blockIdx.z;
    const int t = z >> 4;     // 0: K, 1: V, 2: Q
    const int h = z & 15;
    const float *A, *B, *bias;
    float* C;
    if (t == 0)      { A = g_K; B = hWk + h * DM * DM; bias = hbk + h * DM; C = g_Kh + (size_t)h * SQ * DM; }
    else if (t == 1) { A = g_V; B = hWv + h * DM * DM; bias = hbv + h * DM; C = g_Vh + (size_t)h * SQ * DM; }
    else             { A = g_Q; B = hWq + h * DM * DM; bias = hbq + h * DM; C = g_Qh + (size_t)h * SQ * DM; }
    gemm_tc<64>(A, DM, B, DM, bias, C, DM, DM, blockIdx.y * 128, 0, As, Bs);
}

// ---------------- kernel 2b: transpose Vh -> Vt [h][d][s] ----------------
__global__ void k_transpose()
{
    __shared__ float t[32][33];
    const int h  = blockIdx.z;
    const int s0 = blockIdx.x * 32;
    const int d0 = blockIdx.y * 32;
    const int tx = threadIdx.x, ty = threadIdx.y;
    const float* src = g_Vh + (size_t)h * SQ * DM;
    float* dst = g_Vt + (size_t)h * DM * SQ;
#pragma unroll
    for (int i = 0; i < 4; i++)
        t[ty + i * 8][tx] = src[(size_t)(s0 + ty + i * 8) * DM + d0 + tx];
    __syncthreads();
#pragma unroll
    for (int i = 0; i < 4; i++)
        dst[(size_t)(d0 + ty + i * 8) * SQ + s0 + tx] = t[tx][ty + i * 8];
}

// ---------------- kernel 3: flash attention, tf32 MMA ----------------
// grid (SQ/64, NH), 128 threads (4 warps x m16 rows). Online softmax on frags.
__global__ __launch_bounds__(128) void k_attn()
{
    __shared__ float Ks[64][68];   // [key][d]
    __shared__ float Vs[64][68];   // [d][key]
    const int h    = blockIdx.y;
    const int tid  = threadIdx.x;
    const int lane = tid & 31;
    const int warp = tid >> 5;
    const int g    = lane >> 2;
    const int lam  = lane & 3;
    const int q0   = blockIdx.x * 64 + warp * 16;

    const float* Qb = g_Qh + (size_t)h * SQ * DM;
    const float* Kb = g_Kh + (size_t)h * SQ * DM;
    const float* Vb = g_Vt + (size_t)h * DM * SQ;

    // Q fragments (scale folded in)
    unsigned qa[8][4];
#pragma unroll
    for (int kf = 0; kf < 8; kf++) {
        qa[kf][0] = f2tf(0.125f * Qb[(size_t)(q0 + g) * DM + kf * 8 + lam]);
        qa[kf][1] = f2tf(0.125f * Qb[(size_t)(q0 + g + 8) * DM + kf * 8 + lam]);
        qa[kf][2] = f2tf(0.125f * Qb[(size_t)(q0 + g) * DM + kf * 8 + lam + 4]);
        qa[kf][3] = f2tf(0.125f * Qb[(size_t)(q0 + g + 8) * DM + kf * 8 + lam + 4]);
    }

    float o[8][4];
#pragma unroll
    for (int nf = 0; nf < 8; nf++)
#pragma unroll
        for (int i = 0; i < 4; i++) o[nf][i] = 0.f;
    float m0r = -1e30f, m1r = -1e30f, l0 = 0.f, l1 = 0.f;

    for (int t0 = 0; t0 < SQ; t0 += 64) {
        __syncthreads();
#pragma unroll
        for (int i = 0; i < 8; i++) {
            int f = tid + i * 128;
            int r = f >> 4, c = (f & 15) << 2;
            *reinterpret_cast<float4*>(&Ks[r][c]) =
                *reinterpret_cast<const float4*>(Kb + (size_t)(t0 + r) * DM + c);
            *reinterpret_cast<float4*>(&Vs[r][c]) =
                *reinterpret_cast<const float4*>(Vb + (size_t)r * SQ + t0 + c);
        }
        __syncthreads();

        // S = Q K^T (per warp: m16 x n64)
        float s[8][4];
#pragma unroll
        for (int nf = 0; nf < 8; nf++) {
            s[nf][0] = s[nf][1] = s[nf][2] = s[nf][3] = 0.f;
#pragma unroll
            for (int kf = 0; kf < 8; kf++) {
                unsigned b[2];
                b[0] = f2tf(Ks[nf * 8 + g][kf * 8 + lam]);
                b[1] = f2tf(Ks[nf * 8 + g][kf * 8 + lam + 4]);
                mma_tf32(s[nf], qa[kf], b);
            }
        }

        // online softmax: rows r0 = g (regs 0,1), r1 = g+8 (regs 2,3)
        float mx0 = m0r, mx1 = m1r;
#pragma unroll
        for (int nf = 0; nf < 8; nf++) {
            mx0 = fmaxf(mx0, fmaxf(s[nf][0], s[nf][1]));
            mx1 = fmaxf(mx1, fmaxf(s[nf][2], s[nf][3]));
        }
        mx0 = fmaxf(mx0, __shfl_xor_sync(0xffffffffu, mx0, 1));
        mx0 = fmaxf(mx0, __shfl_xor_sync(0xffffffffu, mx0, 2));
        mx1 = fmaxf(mx1, __shfl_xor_sync(0xffffffffu, mx1, 1));
        mx1 = fmaxf(mx1, __shfl_xor_sync(0xffffffffu, mx1, 2));

        const float c0 = __expf(m0r - mx0);
        const float c1 = __expf(m1r - mx1);
        m0r = mx0; m1r = mx1;

        float ls0 = 0.f, ls1 = 0.f;
#pragma unroll
        for (int nf = 0; nf < 8; nf++) {
            s[nf][0] = __expf(s[nf][0] - mx0);
            s[nf][1] = __expf(s[nf][1] - mx0);
            s[nf][2] = __expf(s[nf][2] - mx1);
            s[nf][3] = __expf(s[nf][3] - mx1);
            ls0 += s[nf][0] + s[nf][1];
            ls1 += s[nf][2] + s[nf][3];
        }
        ls0 += __shfl_xor_sync(0xffffffffu, ls0, 1);
        ls0 += __shfl_xor_sync(0xffffffffu, ls0, 2);
        ls1 += __shfl_xor_sync(0xffffffffu, ls1, 1);
        ls1 += __shfl_xor_sync(0xffffffffu, ls1, 2);
        l0 = l0 * c0 + ls0;
        l1 = l1 * c1 + ls1;
#pragma unroll
        for (int nf = 0; nf < 8; nf++) {
            o[nf][0] *= c0; o[nf][1] *= c0;
            o[nf][2] *= c1; o[nf][3] *= c1;
        }

        // shuffle P from C-layout into A-layout fragments
        unsigned pa[8][4];
        const int src1 = (lane & ~3) | (lam >> 1);
        const int src2 = src1 + 2;
        const bool odd = lam & 1;
#pragma unroll
        for (int f8 = 0; f8 < 8; f8++) {
            float v00 = __shfl_sync(0xffffffffu, s[f8][0], src1);
            float v01 = __shfl_sync(0xffffffffu, s[f8][1], src1);
            float v10 = __shfl_sync(0xffffffffu, s[f8][2], src1);
            float v11 = __shfl_sync(0xffffffffu, s[f8][3], src1);
            float w00 = __shfl_sync(0xffffffffu, s[f8][0], src2);
            float w01 = __shfl_sync(0xffffffffu, s[f8][1], src2);
            float w10 = __shfl_sync(0xffffffffu, s[f8][2], src2);
            float w11 = __shfl_sync(0xffffffffu, s[f8][3], src2);
            pa[f8][0] = f2tf(odd ? v01 : v00);
            pa[f8][1] = f2tf(odd ? v11 : v10);
            pa[f8][2] = f2tf(odd ? w01 : w00);
            pa[f8][3] = f2tf(odd ? w11 : w10);
        }

        // O += P V
#pragma unroll
        for (int nf = 0; nf < 8; nf++) {
#pragma unroll
            for (int kf = 0; kf < 8; kf++) {
                unsigned b[2];
                b[0] = f2tf(Vs[nf * 8 + g][kf * 8 + lam]);
                b[1] = f2tf(Vs[nf * 8 + g][kf * 8 + lam + 4]);
                mma_tf32(o[nf], pa[kf], b);
            }
        }
    }

    const float inv0 = 1.f / l0;
    const float inv1 = 1.f / l1;
#pragma unroll
    for (int nf = 0; nf < 8; nf++) {
        const int col = h * DM + nf * 8 + 2 * lam;
        float2 v0 = make_float2(o[nf][0] * inv0, o[nf][1] * inv0);
        float2 v1 = make_float2(o[nf][2] * inv1, o[nf][3] * inv1);
        *reinterpret_cast<float2*>(g_cat + (size_t)(q0 + g) * EM + col) = v0;
        *reinterpret_cast<float2*>(g_cat + (size_t)(q0 + g + 8) * EM + col) = v1;
    }
}

// ---------------- kernel 4: out-proj ----------------
__global__ __launch_bounds__(256) void k_outproj(const float* __restrict__ Wo,
                                                 const float* __restrict__ bo)
{
    __shared__ float As[128][36];
    __shared__ float Bs[128][36];
    gemm_tc<128>(g_cat, EM, Wo, EM, bo, g_out, EM, EM,
                 blockIdx.y * 128, blockIdx.x * 128, As, Bs);
}

// ---------------- kernel 5: residual + LayerNorm ----------------
__device__ __forceinline__ float block_sum_256(float val, float* sh)
{
    const int lane = threadIdx.x & 31;
    const int w    = threadIdx.x >> 5;
#pragma unroll
    for (int o = 16; o > 0; o >>= 1) val += __shfl_xor_sync(0xffffffffu, val, o);
    if (lane == 0) sh[w] = val;
    __syncthreads();
    if (w == 0) {
        float t = (lane < 8) ? sh[lane] : 0.f;
#pragma unroll
        for (int o = 4; o > 0; o >>= 1) t += __shfl_xor_sync(0xffffffffu, t, o);
        if (lane == 0) sh[0] = t;
    }
    __syncthreads();
    const float r = sh[0];
    __syncthreads();
    return r;
}

__global__ __launch_bounds__(256) void k_ln(const float* __restrict__ x,
                                            const float* __restrict__ gamma,
                                            const float* __restrict__ beta,
                                            float* __restrict__ out)
{
    __shared__ float sh[8];
    const int srow = blockIdx.x;
    const float* orow = g_out + (size_t)srow * EM;
    const float* xrow = x + (size_t)srow * EM;

    float v[4];
    float sum = 0.f;
#pragma unroll
    for (int i = 0; i < 4; i++) {
        const int c = threadIdx.x + i * 256;
        v[i] = orow[c] + xrow[c];
        sum += v[i];
    }
    const float mean = block_sum_256(sum, sh) * (1.f / EM);

    float var = 0.f;
#pragma unroll
    for (int i = 0; i < 4; i++) {
        const float d = v[i] - mean;
        var += d * d;
    }
    const float rstd = rsqrtf(block_sum_256(var, sh) * (1.f / EM) + 1e-5f);

#pragma unroll
    for (int i = 0; i < 4; i++) {
        const int c = threadIdx.x + i * 256;
        out[(size_t)srow * EM + c] = (v[i] - mean) * rstd * gamma[c] + beta[c];
    }
}

// ---------------- launch ----------------
extern "C" void kernel_launch(void* const* d_in, const int* in_sizes, int n_in,
                              void* d_out, int out_size)
{
    const float* x     = (const float*)d_in[0];
    const float* Wk    = (const float*)d_in[1];
    const float* Wq    = (const float*)d_in[2];
    const float* Wv    = (const float*)d_in[3];
    const float* hWk   = (const float*)d_in[4];
    const float* hbk   = (const float*)d_in[5];
    const float* hWv   = (const float*)d_in[6];
    const float* hbv   = (const float*)d_in[7];
    const float* hWq   = (const float*)d_in[8];
    const float* hbq   = (const float*)d_in[9];
    const float* Wo    = (const float*)d_in[10];
    const float* bo    = (const float*)d_in[11];
    const float* gamma = (const float*)d_in[12];
    const float* beta  = (const float*)d_in[13];
    float* out = (float*)d_out;

    k_proj<<<dim3(1, SQ / 128, 3), 128>>>(x, Wk, Wq, Wv);
    k_headlin<<<dim3(1, SQ / 128, 48), 128>>>(hWk, hbk, hWv, hbv, hWq, hbq);
    k_transpose<<<dim3(SQ / 32, DM / 32, NH), dim3(32, 8)>>>();
    k_attn<<<dim3(SQ / 64, NH), 128>>>();
    k_outproj<<<dim3(EM / 128, SQ / 128), 256>>>(Wo, bo);
    k_ln<<<SQ, 256>>>(x, gamma, beta, out);
}

// round 4
// speedup vs baseline: 1.5265x; 1.0941x over previous
#include <cuda_runtime.h>
#include <math.h>

#define SQ 2048
#define EM 1024
#define DM 64
#define NH 16

// ---------------- scratch ----------------
__device__ __align__(16) float g_K[SQ * DM];
__device__ __align__(16) float g_Q[SQ * DM];
__device__ __align__(16) float g_V[SQ * DM];
__device__ __align__(16) float g_Kh[NH * SQ * DM];
__device__ __align__(16) float g_Qh[NH * SQ * DM];
__device__ __align__(16) float g_Vh[NH * SQ * DM];
__device__ __align__(16) float g_Vt[NH * SQ * DM];   // [h][d][s]
__device__ __align__(16) float g_cat[SQ * EM];
__device__ __align__(16) float g_out[SQ * EM];

// ---------------- tf32 helpers ----------------
__device__ __forceinline__ unsigned f2tf(float f) {
    unsigned u;
    asm("cvt.rna.tf32.f32 %0, %1;" : "=r"(u) : "f"(f));
    return u;
}

__device__ __forceinline__ void split_tf32(float v, unsigned& hi, unsigned& lo) {
    hi = f2tf(v);
    lo = f2tf(v - __uint_as_float(hi));
}

__device__ __forceinline__ void mma_tf32(float* d, const unsigned* a, const unsigned* b) {
    asm volatile(
        "mma.sync.aligned.m16n8k8.row.col.f32.tf32.tf32.f32 "
        "{%0,%1,%2,%3},{%4,%5,%6,%7},{%8,%9},{%0,%1,%2,%3};"
        : "+f"(d[0]), "+f"(d[1]), "+f"(d[2]), "+f"(d[3])
        : "r"(a[0]), "r"(a[1]), "r"(a[2]), "r"(a[3]), "r"(b[0]), "r"(b[1]));
}

// ============ 3xTF32 GEMM: C = A @ B^T (+bias), BK=16, smem pre-split ============
// Block BM x BN; WM x WN warps; warp tile (BM/WM) x (BN/WN); frag m16n8k8.
#define SK 20   // smem row stride (words); rows hold BK=16 entries; 20%32 -> conflict-free

template <int BM, int BN, int WM, int WN>
__device__ __forceinline__ void gemm3(const float* __restrict__ A, int lda,
                                      const float* __restrict__ B, int ldb,
                                      const float* __restrict__ bias,
                                      float* __restrict__ C, int ldc,
                                      int Kd, int m0, int n0,
                                      unsigned* Ah, unsigned* Al,
                                      unsigned* Bh, unsigned* Bl)
{
    constexpr int NT = WM * WN * 32;
    constexpr int MF = BM / (WM * 16);
    constexpr int NF = BN / (WN * 8);
    const int tid  = threadIdx.x;
    const int lane = tid & 31;
    const int warp = tid >> 5;
    const int wm   = warp % WM;
    const int wn   = warp / WM;
    const int g    = lane >> 2;
    const int lam  = lane & 3;

    float acc[MF][NF][4];
#pragma unroll
    for (int mf = 0; mf < MF; mf++)
#pragma unroll
        for (int nf = 0; nf < NF; nf++)
#pragma unroll
            for (int i = 0; i < 4; i++) acc[mf][nf][i] = 0.f;

    for (int k0 = 0; k0 < Kd; k0 += 16) {
        __syncthreads();
        // A tile: BM x 16, float4 loads
#pragma unroll
        for (int e = tid; e < BM * 4; e += NT) {
            int r = e >> 2, c = (e & 3) << 2;
            float4 v = *reinterpret_cast<const float4*>(A + (size_t)(m0 + r) * lda + k0 + c);
            split_tf32(v.x, Ah[r * SK + c + 0], Al[r * SK + c + 0]);
            split_tf32(v.y, Ah[r * SK + c + 1], Al[r * SK + c + 1]);
            split_tf32(v.z, Ah[r * SK + c + 2], Al[r * SK + c + 2]);
            split_tf32(v.w, Ah[r * SK + c + 3], Al[r * SK + c + 3]);
        }
        // B tile: BN x 16
#pragma unroll
        for (int e = tid; e < BN * 4; e += NT) {
            int r = e >> 2, c = (e & 3) << 2;
            float4 v = *reinterpret_cast<const float4*>(B + (size_t)(n0 + r) * ldb + k0 + c);
            split_tf32(v.x, Bh[r * SK + c + 0], Bl[r * SK + c + 0]);
            split_tf32(v.y, Bh[r * SK + c + 1], Bl[r * SK + c + 1]);
            split_tf32(v.z, Bh[r * SK + c + 2], Bl[r * SK + c + 2]);
            split_tf32(v.w, Bh[r * SK + c + 3], Bl[r * SK + c + 3]);
        }
        __syncthreads();

#pragma unroll
        for (int kf = 0; kf < 2; kf++) {
            unsigned ah[MF][4], al[MF][4];
#pragma unroll
            for (int mf = 0; mf < MF; mf++) {
                const int r = wm * (MF * 16) + mf * 16 + g;
                ah[mf][0] = Ah[r * SK + kf * 8 + lam];
                ah[mf][1] = Ah[(r + 8) * SK + kf * 8 + lam];
                ah[mf][2] = Ah[r * SK + kf * 8 + lam + 4];
                ah[mf][3] = Ah[(r + 8) * SK + kf * 8 + lam + 4];
                al[mf][0] = Al[r * SK + kf * 8 + lam];
                al[mf][1] = Al[(r + 8) * SK + kf * 8 + lam];
                al[mf][2] = Al[r * SK + kf * 8 + lam + 4];
                al[mf][3] = Al[(r + 8) * SK + kf * 8 + lam + 4];
            }
#pragma unroll
            for (int nf = 0; nf < NF; nf++) {
                const int rb = wn * (NF * 8) + nf * 8 + g;
                unsigned bh[2], bl[2];
                bh[0] = Bh[rb * SK + kf * 8 + lam];
                bh[1] = Bh[rb * SK + kf * 8 + lam + 4];
                bl[0] = Bl[rb * SK + kf * 8 + lam];
                bl[1] = Bl[rb * SK + kf * 8 + lam + 4];
#pragma unroll
                for (int mf = 0; mf < MF; mf++) {
                    mma_tf32(acc[mf][nf], ah[mf], bl);
                    mma_tf32(acc[mf][nf], al[mf], bh);
                    mma_tf32(acc[mf][nf], ah[mf], bh);
                }
            }
        }
    }

#pragma unroll
    for (int mf = 0; mf < MF; mf++) {
        const int row = m0 + wm * (MF * 16) + mf * 16 + g;
#pragma unroll
        for (int nf = 0; nf < NF; nf++) {
            const int col = n0 + wn * (NF * 8) + nf * 8 + 2 * lam;
            float b0 = bias ? bias[col] : 0.f;
            float b1 = bias ? bias[col + 1] : 0.f;
            float2 v0 = make_float2(acc[mf][nf][0] + b0, acc[mf][nf][1] + b1);
            float2 v1 = make_float2(acc[mf][nf][2] + b0, acc[mf][nf][3] + b1);
            *reinterpret_cast<float2*>(C + (size_t)row * ldc + col) = v0;
            *reinterpret_cast<float2*>(C + (size_t)(row + 8) * ldc + col) = v1;
        }
    }
}

// ---------------- kernel 1: shared K/Q/V projections (3xTF32) ----------------
__global__ __launch_bounds__(128) void k_proj(const float* __restrict__ x,
                                              const float* __restrict__ Wk,
                                              const float* __restrict__ Wq,
                                              const float* __restrict__ Wv)
{
    __shared__ unsigned Ah[64 * SK], Al[64 * SK], Bh[64 * SK], Bl[64 * SK];
    const float* W;
    float* C;
    if (blockIdx.z == 0)      { W = Wk; C = g_K; }
    else if (blockIdx.z == 1) { W = Wq; C = g_Q; }
    else                      { W = Wv; C = g_V; }
    gemm3<64, 64, 2, 2>(x, EM, W, EM, nullptr, C, DM, EM, blockIdx.y * 64, 0,
                        Ah, Al, Bh, Bl);
}

// ---------------- kernel 2: per-head linears (3xTF32) ----------------
__global__ __launch_bounds__(128) void k_headlin(const float* __restrict__ hWk,
                                                 const float* __restrict__ hbk,
                                                 const float* __restrict__ hWv,
                                                 const float* __restrict__ hbv,
                                                 const float* __restrict__ hWq,
                                                 const float* __restrict__ hbq)
{
    __shared__ unsigned Ah[64 * SK], Al[64 * SK], Bh[64 * SK], Bl[64 * SK];
    const int z = blockIdx.z;
    const int t = z >> 4;
    const int h = z & 15;
    const float *A, *B, *bias;
    float* C;
    if (t == 0)      { A = g_K; B = hWk + h * DM * DM; bias = hbk + h * DM; C = g_Kh + (size_t)h * SQ * DM; }
    else if (t == 1) { A = g_V; B = hWv + h * DM * DM; bias = hbv + h * DM; C = g_Vh + (size_t)h * SQ * DM; }
    else             { A = g_Q; B = hWq + h * DM * DM; bias = hbq + h * DM; C = g_Qh + (size_t)h * SQ * DM; }
    gemm3<64, 64, 2, 2>(A, DM, B, DM, bias, C, DM, DM, blockIdx.y * 64, 0,
                        Ah, Al, Bh, Bl);
}

// ---------------- kernel 2b: transpose Vh -> Vt [h][d][s] ----------------
__global__ void k_transpose()
{
    __shared__ float t[32][33];
    const int h  = blockIdx.z;
    const int s0 = blockIdx.x * 32;
    const int d0 = blockIdx.y * 32;
    const int tx = threadIdx.x, ty = threadIdx.y;
    const float* src = g_Vh + (size_t)h * SQ * DM;
    float* dst = g_Vt + (size_t)h * DM * SQ;
#pragma unroll
    for (int i = 0; i < 4; i++)
        t[ty + i * 8][tx] = src[(size_t)(s0 + ty + i * 8) * DM + d0 + tx];
    __syncthreads();
#pragma unroll
    for (int i = 0; i < 4; i++)
        dst[(size_t)(d0 + ty + i * 8) * SQ + s0 + tx] = t[tx][ty + i * 8];
}

// ---------------- kernel 3: flash attention, 3xTF32 QK^T + tf32 PV --------------
// grid (SQ/64, NH), 128 threads (4 warps x m16). 32-key tiles; smem pre-split.
#define KS 68   // K-tile row stride: rows hold 64 d-values; 68 >= 64, 68%32==4 -> conflict-free
#define VS 36   // V-tile row stride: rows hold 32 keys; 36 >= 32, 36%32==4 -> conflict-free

__global__ __launch_bounds__(128) void k_attn()
{
    __shared__ unsigned sKh[32 * KS], sKl[32 * KS], sV[64 * VS];
    const int h    = blockIdx.y;
    const int tid  = threadIdx.x;
    const int lane = tid & 31;
    const int warp = tid >> 5;
    const int g    = lane >> 2;
    const int lam  = lane & 3;
    const int q0   = blockIdx.x * 64 + warp * 16;

    const float* Qb = g_Qh + (size_t)h * SQ * DM;
    const float* Kb = g_Kh + (size_t)h * SQ * DM;
    const float* Vb = g_Vt + (size_t)h * DM * SQ;

    // Q fragments hi/lo (scale 0.125 folded in; exact scaling)
    unsigned qh[8][4], ql[8][4];
#pragma unroll
    for (int kf = 0; kf < 8; kf++) {
        split_tf32(0.125f * Qb[(size_t)(q0 + g) * DM + kf * 8 + lam],     qh[kf][0], ql[kf][0]);
        split_tf32(0.125f * Qb[(size_t)(q0 + g + 8) * DM + kf * 8 + lam], qh[kf][1], ql[kf][1]);
        split_tf32(0.125f * Qb[(size_t)(q0 + g) * DM + kf * 8 + lam + 4], qh[kf][2], ql[kf][2]);
        split_tf32(0.125f * Qb[(size_t)(q0 + g + 8) * DM + kf * 8 + lam + 4], qh[kf][3], ql[kf][3]);
    }

    float o[8][4];
#pragma unroll
    for (int nf = 0; nf < 8; nf++)
#pragma unroll
        for (int i = 0; i < 4; i++) o[nf][i] = 0.f;
    float m0r = -1e30f, m1r = -1e30f, l0 = 0.f, l1 = 0.f;

    for (int t0 = 0; t0 < SQ; t0 += 32) {
        __syncthreads();
        // K tile: 32 rows x 64 d, hi/lo split (row stride KS)
#pragma unroll
        for (int i = 0; i < 4; i++) {
            int e = tid + i * 128;                 // 512 float4
            int r = e >> 4, c = (e & 15) << 2;
            float4 v = *reinterpret_cast<const float4*>(Kb + (size_t)(t0 + r) * DM + c);
            split_tf32(v.x, sKh[r * KS + c + 0], sKl[r * KS + c + 0]);
            split_tf32(v.y, sKh[r * KS + c + 1], sKl[r * KS + c + 1]);
            split_tf32(v.z, sKh[r * KS + c + 2], sKl[r * KS + c + 2]);
            split_tf32(v.w, sKh[r * KS + c + 3], sKl[r * KS + c + 3]);
        }
        // V tile: 64 d-rows x 32 keys (transposed source), single tf32 (row stride VS)
#pragma unroll
        for (int i = 0; i < 4; i++) {
            int e = tid + i * 128;                 // 512 float4
            int r = e >> 3, c = (e & 7) << 2;
            float4 v = *reinterpret_cast<const float4*>(Vb + (size_t)r * SQ + t0 + c);
            sV[r * VS + c + 0] = f2tf(v.x);
            sV[r * VS + c + 1] = f2tf(v.y);
            sV[r * VS + c + 2] = f2tf(v.z);
            sV[r * VS + c + 3] = f2tf(v.w);
        }
        __syncthreads();

        // S = Q K^T, 3xTF32 (m16 x n32 per warp)
        float s[4][4];
#pragma unroll
        for (int nf = 0; nf < 4; nf++) {
            s[nf][0] = s[nf][1] = s[nf][2] = s[nf][3] = 0.f;
#pragma unroll
            for (int kf = 0; kf < 8; kf++) {
                const int rb = nf * 8 + g;
                unsigned bh[2], bl[2];
                bh[0] = sKh[rb * KS + kf * 8 + lam];
                bh[1] = sKh[rb * KS + kf * 8 + lam + 4];
                bl[0] = sKl[rb * KS + kf * 8 + lam];
                bl[1] = sKl[rb * KS + kf * 8 + lam + 4];
                mma_tf32(s[nf], qh[kf], bl);
                mma_tf32(s[nf], ql[kf], bh);
                mma_tf32(s[nf], qh[kf], bh);
            }
        }

        // online softmax: rows g (regs 0,1) and g+8 (regs 2,3)
        float mx0 = m0r, mx1 = m1r;
#pragma unroll
        for (int nf = 0; nf < 4; nf++) {
            mx0 = fmaxf(mx0, fmaxf(s[nf][0], s[nf][1]));
            mx1 = fmaxf(mx1, fmaxf(s[nf][2], s[nf][3]));
        }
        mx0 = fmaxf(mx0, __shfl_xor_sync(0xffffffffu, mx0, 1));
        mx0 = fmaxf(mx0, __shfl_xor_sync(0xffffffffu, mx0, 2));
        mx1 = fmaxf(mx1, __shfl_xor_sync(0xffffffffu, mx1, 1));
        mx1 = fmaxf(mx1, __shfl_xor_sync(0xffffffffu, mx1, 2));

        const float c0 = __expf(m0r - mx0);
        const float c1 = __expf(m1r - mx1);
        m0r = mx0; m1r = mx1;

        float ls0 = 0.f, ls1 = 0.f;
#pragma unroll
        for (int nf = 0; nf < 4; nf++) {
            s[nf][0] = __expf(s[nf][0] - mx0);
            s[nf][1] = __expf(s[nf][1] - mx0);
            s[nf][2] = __expf(s[nf][2] - mx1);
            s[nf][3] = __expf(s[nf][3] - mx1);
            ls0 += s[nf][0] + s[nf][1];
            ls1 += s[nf][2] + s[nf][3];
        }
        ls0 += __shfl_xor_sync(0xffffffffu, ls0, 1);
        ls0 += __shfl_xor_sync(0xffffffffu, ls0, 2);
        ls1 += __shfl_xor_sync(0xffffffffu, ls1, 1);
        ls1 += __shfl_xor_sync(0xffffffffu, ls1, 2);
        l0 = l0 * c0 + ls0;
        l1 = l1 * c1 + ls1;
#pragma unroll
        for (int nf = 0; nf < 8; nf++) {
            o[nf][0] *= c0; o[nf][1] *= c0;
            o[nf][2] *= c1; o[nf][3] *= c1;
        }

        // shuffle P (C-layout) -> A-layout fragments
        unsigned pa[4][4];
        const int src1 = (lane & ~3) | (lam >> 1);
        const int src2 = src1 + 2;
        const bool odd = lam & 1;
#pragma unroll
        for (int f8 = 0; f8 < 4; f8++) {
            float v00 = __shfl_sync(0xffffffffu, s[f8][0], src1);
            float v01 = __shfl_sync(0xffffffffu, s[f8][1], src1);
            float v10 = __shfl_sync(0xffffffffu, s[f8][2], src1);
            float v11 = __shfl_sync(0xffffffffu, s[f8][3], src1);
            float w00 = __shfl_sync(0xffffffffu, s[f8][0], src2);
            float w01 = __shfl_sync(0xffffffffu, s[f8][1], src2);
            float w10 = __shfl_sync(0xffffffffu, s[f8][2], src2);
            float w11 = __shfl_sync(0xffffffffu, s[f8][3], src2);
            pa[f8][0] = f2tf(odd ? v01 : v00);
            pa[f8][1] = f2tf(odd ? v11 : v10);
            pa[f8][2] = f2tf(odd ? w01 : w00);
            pa[f8][3] = f2tf(odd ? w11 : w10);
        }

        // O += P V  (m16 x n64, k32)
#pragma unroll
        for (int nf = 0; nf < 8; nf++) {
#pragma unroll
            for (int kf = 0; kf < 4; kf++) {
                unsigned b[2];
                b[0] = sV[(nf * 8 + g) * VS + kf * 8 + lam];
                b[1] = sV[(nf * 8 + g) * VS + kf * 8 + lam + 4];
                mma_tf32(o[nf], pa[kf], b);
            }
        }
    }

    const float inv0 = 1.f / l0;
    const float inv1 = 1.f / l1;
#pragma unroll
    for (int nf = 0; nf < 8; nf++) {
        const int col = h * DM + nf * 8 + 2 * lam;
        float2 v0 = make_float2(o[nf][0] * inv0, o[nf][1] * inv0);
        float2 v1 = make_float2(o[nf][2] * inv1, o[nf][3] * inv1);
        *reinterpret_cast<float2*>(g_cat + (size_t)(q0 + g) * EM + col) = v0;
        *reinterpret_cast<float2*>(g_cat + (size_t)(q0 + g + 8) * EM + col) = v1;
    }
}

// ---------------- kernel 4: out-proj (3xTF32) ----------------
__global__ __launch_bounds__(256) void k_outproj(const float* __restrict__ Wo,
                                                 const float* __restrict__ bo)
{
    __shared__ unsigned Ah[128 * SK], Al[128 * SK], Bh[128 * SK], Bl[128 * SK];
    gemm3<128, 128, 4, 2>(g_cat, EM, Wo, EM, bo, g_out, EM, EM,
                          blockIdx.y * 128, blockIdx.x * 128, Ah, Al, Bh, Bl);
}

// ---------------- kernel 5: residual + LayerNorm ----------------
__device__ __forceinline__ float block_sum_256(float val, float* sh)
{
    const int lane = threadIdx.x & 31;
    const int w    = threadIdx.x >> 5;
#pragma unroll
    for (int o = 16; o > 0; o >>= 1) val += __shfl_xor_sync(0xffffffffu, val, o);
    if (lane == 0) sh[w] = val;
    __syncthreads();
    if (w == 0) {
        float t = (lane < 8) ? sh[lane] : 0.f;
#pragma unroll
        for (int o = 4; o > 0; o >>= 1) t += __shfl_xor_sync(0xffffffffu, t, o);
        if (lane == 0) sh[0] = t;
    }
    __syncthreads();
    const float r = sh[0];
    __syncthreads();
    return r;
}

__global__ __launch_bounds__(256) void k_ln(const float* __restrict__ x,
                                            const float* __restrict__ gamma,
                                            const float* __restrict__ beta,
                                            float* __restrict__ out)
{
    __shared__ float sh[8];
    const int srow = blockIdx.x;
    const float* orow = g_out + (size_t)srow * EM;
    const float* xrow = x + (size_t)srow * EM;

    float v[4];
    float sum = 0.f;
#pragma unroll
    for (int i = 0; i < 4; i++) {
        const int c = threadIdx.x + i * 256;
        v[i] = orow[c] + xrow[c];
        sum += v[i];
    }
    const float mean = block_sum_256(sum, sh) * (1.f / EM);

    float var = 0.f;
#pragma unroll
    for (int i = 0; i < 4; i++) {
        const float d = v[i] - mean;
        var += d * d;
    }
    const float rstd = rsqrtf(block_sum_256(var, sh) * (1.f / EM) + 1e-5f);

#pragma unroll
    for (int i = 0; i < 4; i++) {
        const int c = threadIdx.x + i * 256;
        out[(size_t)srow * EM + c] = (v[i] - mean) * rstd * gamma[c] + beta[c];
    }
}

// ---------------- launch ----------------
extern "C" void kernel_launch(void* const* d_in, const int* in_sizes, int n_in,
                              void* d_out, int out_size)
{
    const float* x     = (const float*)d_in[0];
    const float* Wk    = (const float*)d_in[1];
    const float* Wq    = (const float*)d_in[2];
    const float* Wv    = (const float*)d_in[3];
    const float* hWk   = (const float*)d_in[4];
    const float* hbk   = (const float*)d_in[5];
    const float* hWv   = (const float*)d_in[6];
    const float* hbv   = (const float*)d_in[7];
    const float* hWq   = (const float*)d_in[8];
    const float* hbq   = (const float*)d_in[9];
    const float* Wo    = (const float*)d_in[10];
    const float* bo    = (const float*)d_in[11];
    const float* gamma = (const float*)d_in[12];
    const float* beta  = (const float*)d_in[13];
    float* out = (float*)d_out;

    k_proj<<<dim3(1, SQ / 64, 3), 128>>>(x, Wk, Wq, Wv);
    k_headlin<<<dim3(1, SQ / 64, 48), 128>>>(hWk, hbk, hWv, hbv, hWq, hbq);
    k_transpose<<<dim3(SQ / 32, DM / 32, NH), dim3(32, 8)>>>();
    k_attn<<<dim3(SQ / 64, NH), 128>>>();
    k_outproj<<<dim3(EM / 128, SQ / 128), 256>>>(Wo, bo);
    k_ln<<<SQ, 256>>>(x, gamma, beta, out);
}

// round 5
// speedup vs baseline: 2.0156x; 1.3204x over previous
#include <cuda_runtime.h>
#include <math.h>

#define SQ 2048
#define EM 1024
#define DM 64
#define NH 16

// ---------------- scratch ----------------
__device__ __align__(16) float g_K[SQ * DM];
__device__ __align__(16) float g_Q[SQ * DM];
__device__ __align__(16) float g_V[SQ * DM];
__device__ __align__(16) float g_Kh[NH * SQ * DM];
__device__ __align__(16) float g_Qh[NH * SQ * DM];
__device__ __align__(16) float g_Vh[NH * SQ * DM];
__device__ __align__(16) float g_Vt[NH * SQ * DM];   // [h][d][s]
__device__ __align__(16) float g_cat[SQ * EM];
__device__ __align__(16) float g_out[SQ * EM];

// ---------------- bf16 split helpers ----------------
// pack two floats (x = lower element) into bf16x2
__device__ __forceinline__ unsigned pk2(float x, float y) {
    unsigned r;
    asm("cvt.rn.bf16x2.f32 %0, %1, %2;" : "=r"(r) : "f"(y), "f"(x));
    return r;
}

// split-pack: hi = truncated-bf16 pair (exact residual), lo = rounded residual pair
__device__ __forceinline__ void sp2(float x, float y, unsigned& hi, unsigned& lo) {
    unsigned ux = __float_as_uint(x), uy = __float_as_uint(y);
    hi = __byte_perm(ux, uy, 0x7632);
    float rx = x - __uint_as_float(ux & 0xffff0000u);
    float ry = y - __uint_as_float(uy & 0xffff0000u);
    lo = pk2(rx, ry);
}

__device__ __forceinline__ void mma_bf16(float* d, const unsigned* a, const unsigned* b) {
    asm volatile(
        "mma.sync.aligned.m16n8k16.row.col.f32.bf16.bf16.f32 "
        "{%0,%1,%2,%3},{%4,%5,%6,%7},{%8,%9},{%0,%1,%2,%3};"
        : "+f"(d[0]), "+f"(d[1]), "+f"(d[2]), "+f"(d[3])
        : "r"(a[0]), "r"(a[1]), "r"(a[2]), "r"(a[3]), "r"(b[0]), "r"(b[1]));
}

// ======== split-bf16 3-term GEMM: C = A @ B^T (+bias), BK=32 ========
// smem rows hold 16 bf16x2 pairs; stride SK=20 words -> conflict-free frag LDS.
#define SK 20

template <int BM, int BN, int WM, int WN>
__device__ __forceinline__ void gemm3(const float* __restrict__ A, int lda,
                                      const float* __restrict__ B, int ldb,
                                      const float* __restrict__ bias,
                                      float* __restrict__ C, int ldc,
                                      int Kd, int m0, int n0,
                                      unsigned* Ah, unsigned* Al,
                                      unsigned* Bh, unsigned* Bl)
{
    constexpr int NT = WM * WN * 32;
    constexpr int MF = BM / (WM * 16);
    constexpr int NF = BN / (WN * 8);
    const int tid  = threadIdx.x;
    const int lane = tid & 31;
    const int warp = tid >> 5;
    const int wm   = warp % WM;
    const int wn   = warp / WM;
    const int g    = lane >> 2;
    const int lam  = lane & 3;

    float acc[MF][NF][4];
#pragma unroll
    for (int mf = 0; mf < MF; mf++)
#pragma unroll
        for (int nf = 0; nf < NF; nf++)
#pragma unroll
            for (int i = 0; i < 4; i++) acc[mf][nf][i] = 0.f;

    for (int k0 = 0; k0 < Kd; k0 += 32) {
        __syncthreads();
        // A tile: BM x 32 floats = BM*8 float4
#pragma unroll
        for (int e = tid; e < BM * 8; e += NT) {
            int r = e >> 3, c4 = e & 7;
            float4 v = *reinterpret_cast<const float4*>(A + (size_t)(m0 + r) * lda + k0 + c4 * 4);
            sp2(v.x, v.y, Ah[r * SK + c4 * 2 + 0], Al[r * SK + c4 * 2 + 0]);
            sp2(v.z, v.w, Ah[r * SK + c4 * 2 + 1], Al[r * SK + c4 * 2 + 1]);
        }
        // B tile: BN x 32
#pragma unroll
        for (int e = tid; e < BN * 8; e += NT) {
            int r = e >> 3, c4 = e & 7;
            float4 v = *reinterpret_cast<const float4*>(B + (size_t)(n0 + r) * ldb + k0 + c4 * 4);
            sp2(v.x, v.y, Bh[r * SK + c4 * 2 + 0], Bl[r * SK + c4 * 2 + 0]);
            sp2(v.z, v.w, Bh[r * SK + c4 * 2 + 1], Bl[r * SK + c4 * 2 + 1]);
        }
        __syncthreads();

#pragma unroll
        for (int kc = 0; kc < 2; kc++) {        // two k16 chunks per BK=32
            unsigned ah[MF][4], al[MF][4];
#pragma unroll
            for (int mf = 0; mf < MF; mf++) {
                const int r = wm * (MF * 16) + mf * 16 + g;
                ah[mf][0] = Ah[r * SK + kc * 8 + lam];
                ah[mf][1] = Ah[(r + 8) * SK + kc * 8 + lam];
                ah[mf][2] = Ah[r * SK + kc * 8 + lam + 4];
                ah[mf][3] = Ah[(r + 8) * SK + kc * 8 + lam + 4];
                al[mf][0] = Al[r * SK + kc * 8 + lam];
                al[mf][1] = Al[(r + 8) * SK + kc * 8 + lam];
                al[mf][2] = Al[r * SK + kc * 8 + lam + 4];
                al[mf][3] = Al[(r + 8) * SK + kc * 8 + lam + 4];
            }
#pragma unroll
            for (int nf = 0; nf < NF; nf++) {
                const int rb = wn * (NF * 8) + nf * 8 + g;
                unsigned bh[2], bl[2];
                bh[0] = Bh[rb * SK + kc * 8 + lam];
                bh[1] = Bh[rb * SK + kc * 8 + lam + 4];
                bl[0] = Bl[rb * SK + kc * 8 + lam];
                bl[1] = Bl[rb * SK + kc * 8 + lam + 4];
#pragma unroll
                for (int mf = 0; mf < MF; mf++) {
                    mma_bf16(acc[mf][nf], ah[mf], bl);
                    mma_bf16(acc[mf][nf], al[mf], bh);
                    mma_bf16(acc[mf][nf], ah[mf], bh);
                }
            }
        }
    }

#pragma unroll
    for (int mf = 0; mf < MF; mf++) {
        const int row = m0 + wm * (MF * 16) + mf * 16 + g;
#pragma unroll
        for (int nf = 0; nf < NF; nf++) {
            const int col = n0 + wn * (NF * 8) + nf * 8 + 2 * lam;
            float b0 = bias ? bias[col] : 0.f;
            float b1 = bias ? bias[col + 1] : 0.f;
            float2 v0 = make_float2(acc[mf][nf][0] + b0, acc[mf][nf][1] + b1);
            float2 v1 = make_float2(acc[mf][nf][2] + b0, acc[mf][nf][3] + b1);
            *reinterpret_cast<float2*>(C + (size_t)row * ldc + col) = v0;
            *reinterpret_cast<float2*>(C + (size_t)(row + 8) * ldc + col) = v1;
        }
    }
}

// ---------------- kernel 1: shared K/Q/V projections ----------------
__global__ __launch_bounds__(128) void k_proj(const float* __restrict__ x,
                                              const float* __restrict__ Wk,
                                              const float* __restrict__ Wq,
                                              const float* __restrict__ Wv)
{
    __shared__ unsigned Ah[64 * SK], Al[64 * SK], Bh[64 * SK], Bl[64 * SK];
    const float* W;
    float* C;
    if (blockIdx.z == 0)      { W = Wk; C = g_K; }
    else if (blockIdx.z == 1) { W = Wq; C = g_Q; }
    else                      { W = Wv; C = g_V; }
    gemm3<64, 64, 2, 2>(x, EM, W, EM, nullptr, C, DM, EM, blockIdx.y * 64, 0,
                        Ah, Al, Bh, Bl);
}

// ---------------- kernel 2: per-head linears ----------------
__global__ __launch_bounds__(128) void k_headlin(const float* __restrict__ hWk,
                                                 const float* __restrict__ hbk,
                                                 const float* __restrict__ hWv,
                                                 const float* __restrict__ hbv,
                                                 const float* __restrict__ hWq,
                                                 const float* __restrict__ hbq)
{
    __shared__ unsigned Ah[64 * SK], Al[64 * SK], Bh[64 * SK], Bl[64 * SK];
    const int z = blockIdx.z;
    const int t = z >> 4;
    const int h = z & 15;
    const float *A, *B, *bias;
    float* C;
    if (t == 0)      { A = g_K; B = hWk + h * DM * DM; bias = hbk + h * DM; C = g_Kh + (size_t)h * SQ * DM; }
    else if (t == 1) { A = g_V; B = hWv + h * DM * DM; bias = hbv + h * DM; C = g_Vh + (size_t)h * SQ * DM; }
    else             { A = g_Q; B = hWq + h * DM * DM; bias = hbq + h * DM; C = g_Qh + (size_t)h * SQ * DM; }
    gemm3<64, 64, 2, 2>(A, DM, B, DM, bias, C, DM, DM, blockIdx.y * 64, 0,
                        Ah, Al, Bh, Bl);
}

// ---------------- kernel 2b: transpose Vh -> Vt [h][d][s] ----------------
__global__ void k_transpose()
{
    __shared__ float t[32][33];
    const int h  = blockIdx.z;
    const int s0 = blockIdx.x * 32;
    const int d0 = blockIdx.y * 32;
    const int tx = threadIdx.x, ty = threadIdx.y;
    const float* src = g_Vh + (size_t)h * SQ * DM;
    float* dst = g_Vt + (size_t)h * DM * SQ;
#pragma unroll
    for (int i = 0; i < 4; i++)
        t[ty + i * 8][tx] = src[(size_t)(s0 + ty + i * 8) * DM + d0 + tx];
    __syncthreads();
#pragma unroll
    for (int i = 0; i < 4; i++)
        dst[(size_t)(d0 + ty + i * 8) * SQ + s0 + tx] = t[tx][ty + i * 8];
}

// ---------------- kernel 3: flash attention, split-bf16 3-term ----------------
// grid (SQ/64, NH), 128 threads (4 warps x m16). 32-key tiles; smem pre-split pairs.
#define KS2 36   // K tile: 32 key-rows x 32 d-pairs, stride 36 (36%32==4 -> conflict-free)
#define VS2 20   // V tile: 64 d-rows x 16 key-pairs, stride 20 (20%32==20 -> conflict-free)

__global__ __launch_bounds__(128) void k_attn()
{
    __shared__ unsigned sKh[32 * KS2], sKl[32 * KS2], sVh[64 * VS2], sVl[64 * VS2];
    const int h    = blockIdx.y;
    const int tid  = threadIdx.x;
    const int lane = tid & 31;
    const int warp = tid >> 5;
    const int g    = lane >> 2;
    const int lam  = lane & 3;
    const int q0   = blockIdx.x * 64 + warp * 16;

    const float* Qb = g_Qh + (size_t)h * SQ * DM;
    const float* Kb = g_Kh + (size_t)h * SQ * DM;
    const float* Vb = g_Vt + (size_t)h * DM * SQ;

    // Q fragments hi/lo, packed bf16 pairs, scale 0.125 folded in
    unsigned qh[4][4], ql[4][4];
#pragma unroll
    for (int kc = 0; kc < 4; kc++) {
        float2 v0 = *reinterpret_cast<const float2*>(Qb + (size_t)(q0 + g) * DM + kc * 16 + 2 * lam);
        float2 v1 = *reinterpret_cast<const float2*>(Qb + (size_t)(q0 + g + 8) * DM + kc * 16 + 2 * lam);
        float2 v2 = *reinterpret_cast<const float2*>(Qb + (size_t)(q0 + g) * DM + kc * 16 + 8 + 2 * lam);
        float2 v3 = *reinterpret_cast<const float2*>(Qb + (size_t)(q0 + g + 8) * DM + kc * 16 + 8 + 2 * lam);
        sp2(0.125f * v0.x, 0.125f * v0.y, qh[kc][0], ql[kc][0]);
        sp2(0.125f * v1.x, 0.125f * v1.y, qh[kc][1], ql[kc][1]);
        sp2(0.125f * v2.x, 0.125f * v2.y, qh[kc][2], ql[kc][2]);
        sp2(0.125f * v3.x, 0.125f * v3.y, qh[kc][3], ql[kc][3]);
    }

    float o[8][4];
#pragma unroll
    for (int nf = 0; nf < 8; nf++)
#pragma unroll
        for (int i = 0; i < 4; i++) o[nf][i] = 0.f;
    float m0r = -1e30f, m1r = -1e30f, l0 = 0.f, l1 = 0.f;

    for (int t0 = 0; t0 < SQ; t0 += 32) {
        __syncthreads();
        // K tile: 32 key-rows x 64 d -> 32 pairs/row
#pragma unroll
        for (int i = 0; i < 4; i++) {
            int e = tid + i * 128;                 // 512 float4
            int r = e >> 4, c4 = e & 15;
            float4 v = *reinterpret_cast<const float4*>(Kb + (size_t)(t0 + r) * DM + c4 * 4);
            sp2(v.x, v.y, sKh[r * KS2 + c4 * 2 + 0], sKl[r * KS2 + c4 * 2 + 0]);
            sp2(v.z, v.w, sKh[r * KS2 + c4 * 2 + 1], sKl[r * KS2 + c4 * 2 + 1]);
        }
        // V tile: 64 d-rows x 32 keys -> 16 pairs/row
#pragma unroll
        for (int i = 0; i < 4; i++) {
            int e = tid + i * 128;                 // 512 float4
            int r = e >> 3, c4 = e & 7;
            float4 v = *reinterpret_cast<const float4*>(Vb + (size_t)r * SQ + t0 + c4 * 4);
            sp2(v.x, v.y, sVh[r * VS2 + c4 * 2 + 0], sVl[r * VS2 + c4 * 2 + 0]);
            sp2(v.z, v.w, sVh[r * VS2 + c4 * 2 + 1], sVl[r * VS2 + c4 * 2 + 1]);
        }
        __syncthreads();

        // S = Q K^T, 3-term split-bf16 (m16 x n32 per warp, k=64)
        float s[4][4];
#pragma unroll
        for (int nf = 0; nf < 4; nf++) {
            s[nf][0] = s[nf][1] = s[nf][2] = s[nf][3] = 0.f;
            const int rb = nf * 8 + g;
#pragma unroll
            for (int kc = 0; kc < 4; kc++) {
                unsigned bh[2], bl[2];
                bh[0] = sKh[rb * KS2 + kc * 8 + lam];
                bh[1] = sKh[rb * KS2 + kc * 8 + lam + 4];
                bl[0] = sKl[rb * KS2 + kc * 8 + lam];
                bl[1] = sKl[rb * KS2 + kc * 8 + lam + 4];
                mma_bf16(s[nf], qh[kc], bl);
                mma_bf16(s[nf], ql[kc], bh);
                mma_bf16(s[nf], qh[kc], bh);
            }
        }

        // online softmax: rows g (regs 0,1) and g+8 (regs 2,3)
        float mx0 = m0r, mx1 = m1r;
#pragma unroll
        for (int nf = 0; nf < 4; nf++) {
            mx0 = fmaxf(mx0, fmaxf(s[nf][0], s[nf][1]));
            mx1 = fmaxf(mx1, fmaxf(s[nf][2], s[nf][3]));
        }
        mx0 = fmaxf(mx0, __shfl_xor_sync(0xffffffffu, mx0, 1));
        mx0 = fmaxf(mx0, __shfl_xor_sync(0xffffffffu, mx0, 2));
        mx1 = fmaxf(mx1, __shfl_xor_sync(0xffffffffu, mx1, 1));
        mx1 = fmaxf(mx1, __shfl_xor_sync(0xffffffffu, mx1, 2));

        const float c0 = __expf(m0r - mx0);
        const float c1 = __expf(m1r - mx1);
        m0r = mx0; m1r = mx1;

        float ls0 = 0.f, ls1 = 0.f;
#pragma unroll
        for (int nf = 0; nf < 4; nf++) {
            s[nf][0] = __expf(s[nf][0] - mx0);
            s[nf][1] = __expf(s[nf][1] - mx0);
            s[nf][2] = __expf(s[nf][2] - mx1);
            s[nf][3] = __expf(s[nf][3] - mx1);
            ls0 += s[nf][0] + s[nf][1];
            ls1 += s[nf][2] + s[nf][3];
        }
        ls0 += __shfl_xor_sync(0xffffffffu, ls0, 1);
        ls0 += __shfl_xor_sync(0xffffffffu, ls0, 2);
        ls1 += __shfl_xor_sync(0xffffffffu, ls1, 1);
        ls1 += __shfl_xor_sync(0xffffffffu, ls1, 2);
        l0 = l0 * c0 + ls0;
        l1 = l1 * c1 + ls1;
#pragma unroll
        for (int nf = 0; nf < 8; nf++) {
            o[nf][0] *= c0; o[nf][1] *= c0;
            o[nf][2] *= c1; o[nf][3] *= c1;
        }

        // P: fp16-family C-layout == bf16 A-layout -> pack directly, no shuffles.
        unsigned ph[2][4], pl[2][4];
#pragma unroll
        for (int kc = 0; kc < 2; kc++) {
            sp2(s[2 * kc][0],     s[2 * kc][1],     ph[kc][0], pl[kc][0]);
            sp2(s[2 * kc][2],     s[2 * kc][3],     ph[kc][1], pl[kc][1]);
            sp2(s[2 * kc + 1][0], s[2 * kc + 1][1], ph[kc][2], pl[kc][2]);
            sp2(s[2 * kc + 1][2], s[2 * kc + 1][3], ph[kc][3], pl[kc][3]);
        }

        // O += P V, 3-term (m16 x n64, k=32 keys)
#pragma unroll
        for (int nf = 0; nf < 8; nf++) {
            const int rb = nf * 8 + g;
#pragma unroll
            for (int kc = 0; kc < 2; kc++) {
                unsigned bh[2], bl[2];
                bh[0] = sVh[rb * VS2 + kc * 8 + lam];
                bh[1] = sVh[rb * VS2 + kc * 8 + lam + 4];
                bl[0] = sVl[rb * VS2 + kc * 8 + lam];
                bl[1] = sVl[rb * VS2 + kc * 8 + lam + 4];
                mma_bf16(o[nf], ph[kc], bl);
                mma_bf16(o[nf], pl[kc], bh);
                mma_bf16(o[nf], ph[kc], bh);
            }
        }
    }

    const float inv0 = 1.f / l0;
    const float inv1 = 1.f / l1;
#pragma unroll
    for (int nf = 0; nf < 8; nf++) {
        const int col = h * DM + nf * 8 + 2 * lam;
        float2 v0 = make_float2(o[nf][0] * inv0, o[nf][1] * inv0);
        float2 v1 = make_float2(o[nf][2] * inv1, o[nf][3] * inv1);
        *reinterpret_cast<float2*>(g_cat + (size_t)(q0 + g) * EM + col) = v0;
        *reinterpret_cast<float2*>(g_cat + (size_t)(q0 + g + 8) * EM + col) = v1;
    }
}

// ---------------- kernel 4: out-proj ----------------
__global__ __launch_bounds__(256) void k_outproj(const float* __restrict__ Wo,
                                                 const float* __restrict__ bo)
{
    __shared__ unsigned Ah[128 * SK], Al[128 * SK], Bh[128 * SK], Bl[128 * SK];
    gemm3<128, 128, 4, 2>(g_cat, EM, Wo, EM, bo, g_out, EM, EM,
                          blockIdx.y * 128, blockIdx.x * 128, Ah, Al, Bh, Bl);
}

// ---------------- kernel 5: residual + LayerNorm ----------------
__device__ __forceinline__ float block_sum_256(float val, float* sh)
{
    const int lane = threadIdx.x & 31;
    const int w    = threadIdx.x >> 5;
#pragma unroll
    for (int o = 16; o > 0; o >>= 1) val += __shfl_xor_sync(0xffffffffu, val, o);
    if (lane == 0) sh[w] = val;
    __syncthreads();
    if (w == 0) {
        float t = (lane < 8) ? sh[lane] : 0.f;
#pragma unroll
        for (int o = 4; o > 0; o >>= 1) t += __shfl_xor_sync(0xffffffffu, t, o);
        if (lane == 0) sh[0] = t;
    }
    __syncthreads();
    const float r = sh[0];
    __syncthreads();
    return r;
}

__global__ __launch_bounds__(256) void k_ln(const float* __restrict__ x,
                                            const float* __restrict__ gamma,
                                            const float* __restrict__ beta,
                                            float* __restrict__ out)
{
    __shared__ float sh[8];
    const int srow = blockIdx.x;
    const float* orow = g_out + (size_t)srow * EM;
    const float* xrow = x + (size_t)srow * EM;

    float v[4];
    float sum = 0.f;
#pragma unroll
    for (int i = 0; i < 4; i++) {
        const int c = threadIdx.x + i * 256;
        v[i] = orow[c] + xrow[c];
        sum += v[i];
    }
    const float mean = block_sum_256(sum, sh) * (1.f / EM);

    float var = 0.f;
#pragma unroll
    for (int i = 0; i < 4; i++) {
        const float d = v[i] - mean;
        var += d * d;
    }
    const float rstd = rsqrtf(block_sum_256(var, sh) * (1.f / EM) + 1e-5f);

#pragma unroll
    for (int i = 0; i < 4; i++) {
        const int c = threadIdx.x + i * 256;
        out[(size_t)srow * EM + c] = (v[i] - mean) * rstd * gamma[c] + beta[c];
    }
}

// ---------------- launch ----------------
extern "C" void kernel_launch(void* const* d_in, const int* in_sizes, int n_in,
                              void* d_out, int out_size)
{
    const float* x     = (const float*)d_in[0];
    const float* Wk    = (const float*)d_in[1];
    const float* Wq    = (const float*)d_in[2];
    const float* Wv    = (const float*)d_in[3];
    const float* hWk   = (const float*)d_in[4];
    const float* hbk   = (const float*)d_in[5];
    const float* hWv   = (const float*)d_in[6];
    const float* hbv   = (const float*)d_in[7];
    const float* hWq   = (const float*)d_in[8];
    const float* hbq   = (const float*)d_in[9];
    const float* Wo    = (const float*)d_in[10];
    const float* bo    = (const float*)d_in[11];
    const float* gamma = (const float*)d_in[12];
    const float* beta  = (const float*)d_in[13];
    float* out = (float*)d_out;

    k_proj<<<dim3(1, SQ / 64, 3), 128>>>(x, Wk, Wq, Wv);
    k_headlin<<<dim3(1, SQ / 64, 48), 128>>>(hWk, hbk, hWv, hbv, hWq, hbq);
    k_transpose<<<dim3(SQ / 32, DM / 32, NH), dim3(32, 8)>>>();
    k_attn<<<dim3(SQ / 64, NH), 128>>>();
    k_outproj<<<dim3(EM / 128, SQ / 128), 256>>>(Wo, bo);
    k_ln<<<SQ, 256>>>(x, gamma, beta, out);
}

// round 6
// speedup vs baseline: 2.1482x; 1.0658x over previous
#include <cuda_runtime.h>
#include <math.h>

#define SQ 2048
#define EM 1024
#define DM 64
#define NH 16

// ---------------- scratch: packed bf16x2 hi/lo pair arrays ----------------
__device__ __align__(16) unsigned g_pKh[SQ * 32], g_pKl[SQ * 32];
__device__ __align__(16) unsigned g_pQh[SQ * 32], g_pQl[SQ * 32];
__device__ __align__(16) unsigned g_pVh[SQ * 32], g_pVl[SQ * 32];
__device__ __align__(16) unsigned g_hKh[NH * SQ * 32], g_hKl[NH * SQ * 32];
__device__ __align__(16) unsigned g_hQh[NH * SQ * 32], g_hQl[NH * SQ * 32];
__device__ __align__(16) float    g_Vh[NH * SQ * DM];
__device__ __align__(16) unsigned g_tVh[NH * DM * (SQ / 2)], g_tVl[NH * DM * (SQ / 2)];
__device__ __align__(16) unsigned g_ch[SQ * (EM / 2)], g_cl[SQ * (EM / 2)];
__device__ __align__(16) unsigned g_Woh[EM * (EM / 2)], g_Wol[EM * (EM / 2)];
__device__ __align__(16) float    g_out[SQ * EM];

// ---------------- bf16 split helpers ----------------
__device__ __forceinline__ unsigned pk2(float x, float y) {
    unsigned r;
    asm("cvt.rn.bf16x2.f32 %0, %1, %2;" : "=r"(r) : "f"(y), "f"(x));
    return r;
}

// hi = truncated-bf16 pair (exact residual), lo = rounded residual pair
__device__ __forceinline__ void sp2(float x, float y, unsigned& hi, unsigned& lo) {
    unsigned ux = __float_as_uint(x), uy = __float_as_uint(y);
    hi = __byte_perm(ux, uy, 0x7632);
    float rx = x - __uint_as_float(ux & 0xffff0000u);
    float ry = y - __uint_as_float(uy & 0xffff0000u);
    lo = pk2(rx, ry);
}

__device__ __forceinline__ void mma_bf16(float* d, const unsigned* a, const unsigned* b) {
    asm volatile(
        "mma.sync.aligned.m16n8k16.row.col.f32.bf16.bf16.f32 "
        "{%0,%1,%2,%3},{%4,%5,%6,%7},{%8,%9},{%0,%1,%2,%3};"
        : "+f"(d[0]), "+f"(d[1]), "+f"(d[2]), "+f"(d[3])
        : "r"(a[0]), "r"(a[1]), "r"(a[2]), "r"(a[3]), "r"(b[0]), "r"(b[1]));
}

// ======== split-bf16 3-term GEMM: C = A @ B^T (+bias), BK=32 ========
#define SK 20   // smem row stride (words); 16 pairs per row

template <int BM, int BN, int WM, int WN, bool ASPLIT, bool BSPLIT, bool OUTPAIR>
__device__ __forceinline__ void gemm3x(
    const float* A, const unsigned* Aph, const unsigned* Apl, int lda,   // f32 elems | pairs
    const float* B, const unsigned* Bph, const unsigned* Bpl, int ldb,
    const float* bias,
    float* C, unsigned* Cph, unsigned* Cpl, int ldc,                     // f32 elems | pairs
    float oscale, int Kd, int m0, int n0,
    unsigned* Ah, unsigned* Al, unsigned* Bh, unsigned* Bl)
{
    constexpr int NT = WM * WN * 32;
    constexpr int MF = BM / (WM * 16);
    constexpr int NF = BN / (WN * 8);
    const int tid  = threadIdx.x;
    const int lane = tid & 31;
    const int warp = tid >> 5;
    const int wm   = warp % WM;
    const int wn   = warp / WM;
    const int g    = lane >> 2;
    const int lam  = lane & 3;

    float acc[MF][NF][4];
#pragma unroll
    for (int mf = 0; mf < MF; mf++)
#pragma unroll
        for (int nf = 0; nf < NF; nf++)
#pragma unroll
            for (int i = 0; i < 4; i++) acc[mf][nf][i] = 0.f;

    for (int k0 = 0; k0 < Kd; k0 += 32) {
        __syncthreads();
        if (ASPLIT) {
#pragma unroll
            for (int e = tid; e < BM * 4; e += NT) {
                int r = e >> 2, c = e & 3;
                size_t off = (size_t)(m0 + r) * lda + (k0 >> 1) + c * 4;
                *reinterpret_cast<uint4*>(Ah + r * SK + c * 4) = *reinterpret_cast<const uint4*>(Aph + off);
                *reinterpret_cast<uint4*>(Al + r * SK + c * 4) = *reinterpret_cast<const uint4*>(Apl + off);
            }
        } else {
#pragma unroll
            for (int e = tid; e < BM * 8; e += NT) {
                int r = e >> 3, c4 = e & 7;
                float4 v = *reinterpret_cast<const float4*>(A + (size_t)(m0 + r) * lda + k0 + c4 * 4);
                sp2(v.x, v.y, Ah[r * SK + c4 * 2 + 0], Al[r * SK + c4 * 2 + 0]);
                sp2(v.z, v.w, Ah[r * SK + c4 * 2 + 1], Al[r * SK + c4 * 2 + 1]);
            }
        }
        if (BSPLIT) {
#pragma unroll
            for (int e = tid; e < BN * 4; e += NT) {
                int r = e >> 2, c = e & 3;
                size_t off = (size_t)(n0 + r) * ldb + (k0 >> 1) + c * 4;
                *reinterpret_cast<uint4*>(Bh + r * SK + c * 4) = *reinterpret_cast<const uint4*>(Bph + off);
                *reinterpret_cast<uint4*>(Bl + r * SK + c * 4) = *reinterpret_cast<const uint4*>(Bpl + off);
            }
        } else {
#pragma unroll
            for (int e = tid; e < BN * 8; e += NT) {
                int r = e >> 3, c4 = e & 7;
                float4 v = *reinterpret_cast<const float4*>(B + (size_t)(n0 + r) * ldb + k0 + c4 * 4);
                sp2(v.x, v.y, Bh[r * SK + c4 * 2 + 0], Bl[r * SK + c4 * 2 + 0]);
                sp2(v.z, v.w, Bh[r * SK + c4 * 2 + 1], Bl[r * SK + c4 * 2 + 1]);
            }
        }
        __syncthreads();

#pragma unroll
        for (int kc = 0; kc < 2; kc++) {
            unsigned ah[MF][4], al[MF][4];
#pragma unroll
            for (int mf = 0; mf < MF; mf++) {
                const int r = wm * (MF * 16) + mf * 16 + g;
                ah[mf][0] = Ah[r * SK + kc * 8 + lam];
                ah[mf][1] = Ah[(r + 8) * SK + kc * 8 + lam];
                ah[mf][2] = Ah[r * SK + kc * 8 + lam + 4];
                ah[mf][3] = Ah[(r + 8) * SK + kc * 8 + lam + 4];
                al[mf][0] = Al[r * SK + kc * 8 + lam];
                al[mf][1] = Al[(r + 8) * SK + kc * 8 + lam];
                al[mf][2] = Al[r * SK + kc * 8 + lam + 4];
                al[mf][3] = Al[(r + 8) * SK + kc * 8 + lam + 4];
            }
#pragma unroll
            for (int nf = 0; nf < NF; nf++) {
                const int rb = wn * (NF * 8) + nf * 8 + g;
                unsigned bh[2], bl[2];
                bh[0] = Bh[rb * SK + kc * 8 + lam];
                bh[1] = Bh[rb * SK + kc * 8 + lam + 4];
                bl[0] = Bl[rb * SK + kc * 8 + lam];
                bl[1] = Bl[rb * SK + kc * 8 + lam + 4];
#pragma unroll
                for (int mf = 0; mf < MF; mf++) {
                    mma_bf16(acc[mf][nf], ah[mf], bl);
                    mma_bf16(acc[mf][nf], al[mf], bh);
                    mma_bf16(acc[mf][nf], ah[mf], bh);
                }
            }
        }
    }

#pragma unroll
    for (int mf = 0; mf < MF; mf++) {
        const int row = m0 + wm * (MF * 16) + mf * 16 + g;
#pragma unroll
        for (int nf = 0; nf < NF; nf++) {
            if (OUTPAIR) {
                const int pc = (n0 >> 1) + wn * (NF * 4) + nf * 4 + lam;
                float b0 = bias ? bias[2 * pc] : 0.f;
                float b1 = bias ? bias[2 * pc + 1] : 0.f;
                unsigned hi, lo;
                sp2((acc[mf][nf][0] + b0) * oscale, (acc[mf][nf][1] + b1) * oscale, hi, lo);
                Cph[(size_t)row * ldc + pc] = hi;
                Cpl[(size_t)row * ldc + pc] = lo;
                sp2((acc[mf][nf][2] + b0) * oscale, (acc[mf][nf][3] + b1) * oscale, hi, lo);
                Cph[(size_t)(row + 8) * ldc + pc] = hi;
                Cpl[(size_t)(row + 8) * ldc + pc] = lo;
            } else {
                const int col = n0 + wn * (NF * 8) + nf * 8 + 2 * lam;
                float b0 = bias ? bias[col] : 0.f;
                float b1 = bias ? bias[col + 1] : 0.f;
                float2 v0 = make_float2(acc[mf][nf][0] + b0, acc[mf][nf][1] + b1);
                float2 v1 = make_float2(acc[mf][nf][2] + b0, acc[mf][nf][3] + b1);
                *reinterpret_cast<float2*>(C + (size_t)row * ldc + col) = v0;
                *reinterpret_cast<float2*>(C + (size_t)(row + 8) * ldc + col) = v1;
            }
        }
    }
}

// ---------------- kernel 0: pre-split Wo ----------------
__global__ __launch_bounds__(128) void k_splitW(const float* __restrict__ Wo)
{
    const int r = blockIdx.x;
#pragma unroll
    for (int i = 0; i < 2; i++) {
        int c4 = threadIdx.x + i * 128;
        float4 v = *reinterpret_cast<const float4*>(Wo + (size_t)r * EM + c4 * 4);
        unsigned h0, l0, h1, l1;
        sp2(v.x, v.y, h0, l0);
        sp2(v.z, v.w, h1, l1);
        g_Woh[(size_t)r * 512 + c4 * 2 + 0] = h0;
        g_Wol[(size_t)r * 512 + c4 * 2 + 0] = l0;
        g_Woh[(size_t)r * 512 + c4 * 2 + 1] = h1;
        g_Wol[(size_t)r * 512 + c4 * 2 + 1] = l1;
    }
}

// ---------------- kernel 1: shared projections -> split pairs ----------------
__global__ __launch_bounds__(128) void k_proj(const float* __restrict__ x,
                                              const float* __restrict__ Wk,
                                              const float* __restrict__ Wq,
                                              const float* __restrict__ Wv)
{
    __shared__ unsigned Ah[64 * SK], Al[64 * SK], Bh[64 * SK], Bl[64 * SK];
    const float* W;
    unsigned *Ch, *Cl;
    if (blockIdx.z == 0)      { W = Wk; Ch = g_pKh; Cl = g_pKl; }
    else if (blockIdx.z == 1) { W = Wq; Ch = g_pQh; Cl = g_pQl; }
    else                      { W = Wv; Ch = g_pVh; Cl = g_pVl; }
    gemm3x<64, 64, 2, 2, false, false, true>(
        x, nullptr, nullptr, EM, W, nullptr, nullptr, EM, nullptr,
        nullptr, Ch, Cl, 32, 1.f, EM, blockIdx.y * 64, 0, Ah, Al, Bh, Bl);
}

// ---------------- kernel 2: per-head linears ----------------
__global__ __launch_bounds__(128) void k_headlin(const float* __restrict__ hWk,
                                                 const float* __restrict__ hbk,
                                                 const float* __restrict__ hWv,
                                                 const float* __restrict__ hbv,
                                                 const float* __restrict__ hWq,
                                                 const float* __restrict__ hbq)
{
    __shared__ unsigned Ah[64 * SK], Al[64 * SK], Bh[64 * SK], Bl[64 * SK];
    const int z = blockIdx.z;
    const int t = z >> 4;
    const int h = z & 15;
    const int m0 = blockIdx.y * 64;
    if (t == 0) {
        gemm3x<64, 64, 2, 2, true, false, true>(
            nullptr, g_pKh, g_pKl, 32, hWk + h * DM * DM, nullptr, nullptr, DM, hbk + h * DM,
            nullptr, g_hKh + (size_t)h * SQ * 32, g_hKl + (size_t)h * SQ * 32, 32,
            1.f, DM, m0, 0, Ah, Al, Bh, Bl);
    } else if (t == 2) {
        gemm3x<64, 64, 2, 2, true, false, true>(
            nullptr, g_pQh, g_pQl, 32, hWq + h * DM * DM, nullptr, nullptr, DM, hbq + h * DM,
            nullptr, g_hQh + (size_t)h * SQ * 32, g_hQl + (size_t)h * SQ * 32, 32,
            0.125f, DM, m0, 0, Ah, Al, Bh, Bl);
    } else {
        gemm3x<64, 64, 2, 2, true, false, false>(
            nullptr, g_pVh, g_pVl, 32, hWv + h * DM * DM, nullptr, nullptr, DM, hbv + h * DM,
            g_Vh + (size_t)h * SQ * DM, nullptr, nullptr, DM,
            1.f, DM, m0, 0, Ah, Al, Bh, Bl);
    }
}

// ---------------- kernel 2b: transpose Vh -> split Vt pairs [h][d][s/2] -------
__global__ void k_transpose()
{
    __shared__ float t[32][33];
    const int h  = blockIdx.z;
    const int s0 = blockIdx.x * 32;
    const int d0 = blockIdx.y * 32;
    const int tx = threadIdx.x, ty = threadIdx.y;
    const float* src = g_Vh + (size_t)h * SQ * DM;
#pragma unroll
    for (int i = 0; i < 4; i++)
        t[ty + i * 8][tx] = src[(size_t)(s0 + ty + i * 8) * DM + d0 + tx];
    __syncthreads();
    const int tid = ty * 32 + tx;
#pragma unroll
    for (int i = 0; i < 2; i++) {
        int o  = tid + i * 256;
        int dl = o >> 4, p = o & 15;
        unsigned hi, lo;
        sp2(t[2 * p][dl], t[2 * p + 1][dl], hi, lo);
        size_t idx = ((size_t)h * DM + d0 + dl) * (SQ / 2) + (s0 >> 1) + p;
        g_tVh[idx] = hi;
        g_tVl[idx] = lo;
    }
}

// ---------------- kernel 3: flash attention, all-pre-split, 64-key tiles -------
#define AS 36   // smem row stride (words): 32 pairs/row, 36%32==4 -> conflict-free

__global__ __launch_bounds__(128) void k_attn()
{
    __shared__ unsigned sKh[64 * AS], sKl[64 * AS], sVh[64 * AS], sVl[64 * AS];
    const int h    = blockIdx.y;
    const int tid  = threadIdx.x;
    const int lane = tid & 31;
    const int warp = tid >> 5;
    const int g    = lane >> 2;
    const int lam  = lane & 3;
    const int q0   = blockIdx.x * 64 + warp * 16;

    const unsigned* Qh_ = g_hQh + (size_t)h * SQ * 32;
    const unsigned* Ql_ = g_hQl + (size_t)h * SQ * 32;
    const unsigned* Kh_ = g_hKh + (size_t)h * SQ * 32;
    const unsigned* Kl_ = g_hKl + (size_t)h * SQ * 32;
    const unsigned* Vh_ = g_tVh + (size_t)h * DM * (SQ / 2);
    const unsigned* Vl_ = g_tVl + (size_t)h * DM * (SQ / 2);

    // Q fragments (pre-split, pre-scaled)
    unsigned qh[4][4], ql[4][4];
#pragma unroll
    for (int kc = 0; kc < 4; kc++) {
        qh[kc][0] = Qh_[(size_t)(q0 + g) * 32 + kc * 8 + lam];
        qh[kc][1] = Qh_[(size_t)(q0 + g + 8) * 32 + kc * 8 + lam];
        qh[kc][2] = Qh_[(size_t)(q0 + g) * 32 + kc * 8 + 4 + lam];
        qh[kc][3] = Qh_[(size_t)(q0 + g + 8) * 32 + kc * 8 + 4 + lam];
        ql[kc][0] = Ql_[(size_t)(q0 + g) * 32 + kc * 8 + lam];
        ql[kc][1] = Ql_[(size_t)(q0 + g + 8) * 32 + kc * 8 + lam];
        ql[kc][2] = Ql_[(size_t)(q0 + g) * 32 + kc * 8 + 4 + lam];
        ql[kc][3] = Ql_[(size_t)(q0 + g + 8) * 32 + kc * 8 + 4 + lam];
    }

    float o[8][4];
#pragma unroll
    for (int nf = 0; nf < 8; nf++)
#pragma unroll
        for (int i = 0; i < 4; i++) o[nf][i] = 0.f;
    float m0r = -1e30f, m1r = -1e30f, l0 = 0.f, l1 = 0.f;

    for (int t0 = 0; t0 < SQ; t0 += 64) {
        __syncthreads();
        // pure uint4 copies: K 64x32 pairs, V 64x32 pairs
#pragma unroll
        for (int i = 0; i < 4; i++) {
            int e = tid + i * 128;
            int r = e >> 3, c = e & 7;
            size_t ko = (size_t)(t0 + r) * 32 + c * 4;
            *reinterpret_cast<uint4*>(sKh + r * AS + c * 4) = *reinterpret_cast<const uint4*>(Kh_ + ko);
            *reinterpret_cast<uint4*>(sKl + r * AS + c * 4) = *reinterpret_cast<const uint4*>(Kl_ + ko);
            size_t vo = (size_t)r * (SQ / 2) + (t0 >> 1) + c * 4;
            *reinterpret_cast<uint4*>(sVh + r * AS + c * 4) = *reinterpret_cast<const uint4*>(Vh_ + vo);
            *reinterpret_cast<uint4*>(sVl + r * AS + c * 4) = *reinterpret_cast<const uint4*>(Vl_ + vo);
        }
        __syncthreads();

        // S = Q K^T, 3-term (m16 x n64 per warp, k=64)
        float s[8][4];
#pragma unroll
        for (int nf = 0; nf < 8; nf++) {
            s[nf][0] = s[nf][1] = s[nf][2] = s[nf][3] = 0.f;
            const int rb = nf * 8 + g;
#pragma unroll
            for (int kc = 0; kc < 4; kc++) {
                unsigned bh[2], bl[2];
                bh[0] = sKh[rb * AS + kc * 8 + lam];
                bh[1] = sKh[rb * AS + kc * 8 + 4 + lam];
                bl[0] = sKl[rb * AS + kc * 8 + lam];
                bl[1] = sKl[rb * AS + kc * 8 + 4 + lam];
                mma_bf16(s[nf], qh[kc], bl);
                mma_bf16(s[nf], ql[kc], bh);
                mma_bf16(s[nf], qh[kc], bh);
            }
        }

        // online softmax: rows g (regs 0,1) and g+8 (regs 2,3)
        float mx0 = m0r, mx1 = m1r;
#pragma unroll
        for (int nf = 0; nf < 8; nf++) {
            mx0 = fmaxf(mx0, fmaxf(s[nf][0], s[nf][1]));
            mx1 = fmaxf(mx1, fmaxf(s[nf][2], s[nf][3]));
        }
        mx0 = fmaxf(mx0, __shfl_xor_sync(0xffffffffu, mx0, 1));
        mx0 = fmaxf(mx0, __shfl_xor_sync(0xffffffffu, mx0, 2));
        mx1 = fmaxf(mx1, __shfl_xor_sync(0xffffffffu, mx1, 1));
        mx1 = fmaxf(mx1, __shfl_xor_sync(0xffffffffu, mx1, 2));

        const float c0 = __expf(m0r - mx0);
        const float c1 = __expf(m1r - mx1);
        m0r = mx0; m1r = mx1;

        float ls0 = 0.f, ls1 = 0.f;
#pragma unroll
        for (int nf = 0; nf < 8; nf++) {
            s[nf][0] = __expf(s[nf][0] - mx0);
            s[nf][1] = __expf(s[nf][1] - mx0);
            s[nf][2] = __expf(s[nf][2] - mx1);
            s[nf][3] = __expf(s[nf][3] - mx1);
            ls0 += s[nf][0] + s[nf][1];
            ls1 += s[nf][2] + s[nf][3];
        }
        ls0 += __shfl_xor_sync(0xffffffffu, ls0, 1);
        ls0 += __shfl_xor_sync(0xffffffffu, ls0, 2);
        ls1 += __shfl_xor_sync(0xffffffffu, ls1, 1);
        ls1 += __shfl_xor_sync(0xffffffffu, ls1, 2);
        l0 = l0 * c0 + ls0;
        l1 = l1 * c1 + ls1;
#pragma unroll
        for (int nf = 0; nf < 8; nf++) {
            o[nf][0] *= c0; o[nf][1] *= c0;
            o[nf][2] *= c1; o[nf][3] *= c1;
        }

        // P: C-layout == A-layout -> pack directly (k=64 -> 4 chunks)
        unsigned ph[4][4], pl[4][4];
#pragma unroll
        for (int kc = 0; kc < 4; kc++) {
            sp2(s[2 * kc][0],     s[2 * kc][1],     ph[kc][0], pl[kc][0]);
            sp2(s[2 * kc][2],     s[2 * kc][3],     ph[kc][1], pl[kc][1]);
            sp2(s[2 * kc + 1][0], s[2 * kc + 1][1], ph[kc][2], pl[kc][2]);
            sp2(s[2 * kc + 1][2], s[2 * kc + 1][3], ph[kc][3], pl[kc][3]);
        }

        // O += P V, 3-term (m16 x n64, k=64 keys)
#pragma unroll
        for (int nf = 0; nf < 8; nf++) {
            const int rb = nf * 8 + g;
#pragma unroll
            for (int kc = 0; kc < 4; kc++) {
                unsigned bh[2], bl[2];
                bh[0] = sVh[rb * AS + kc * 8 + lam];
                bh[1] = sVh[rb * AS + kc * 8 + 4 + lam];
                bl[0] = sVl[rb * AS + kc * 8 + lam];
                bl[1] = sVl[rb * AS + kc * 8 + 4 + lam];
                mma_bf16(o[nf], ph[kc], bl);
                mma_bf16(o[nf], pl[kc], bh);
                mma_bf16(o[nf], ph[kc], bh);
            }
        }
    }

    // epilogue: write cat as split pairs
    const float inv0 = 1.f / l0;
    const float inv1 = 1.f / l1;
#pragma unroll
    for (int nf = 0; nf < 8; nf++) {
        const int pc = h * 32 + nf * 4 + lam;
        unsigned hi, lo;
        sp2(o[nf][0] * inv0, o[nf][1] * inv0, hi, lo);
        g_ch[(size_t)(q0 + g) * 512 + pc] = hi;
        g_cl[(size_t)(q0 + g) * 512 + pc] = lo;
        sp2(o[nf][2] * inv1, o[nf][3] * inv1, hi, lo);
        g_ch[(size_t)(q0 + g + 8) * 512 + pc] = hi;
        g_cl[(size_t)(q0 + g + 8) * 512 + pc] = lo;
    }
}

// ---------------- kernel 4: out-proj (pre-split A and B) ----------------
__global__ __launch_bounds__(256) void k_outproj(const float* __restrict__ bo)
{
    __shared__ unsigned Ah[128 * SK], Al[128 * SK], Bh[128 * SK], Bl[128 * SK];
    gemm3x<128, 128, 4, 2, true, true, false>(
        nullptr, g_ch, g_cl, 512, nullptr, g_Woh, g_Wol, 512, bo,
        g_out, nullptr, nullptr, EM, 1.f, EM,
        blockIdx.y * 128, blockIdx.x * 128, Ah, Al, Bh, Bl);
}

// ---------------- kernel 5: residual + LayerNorm ----------------
__device__ __forceinline__ float block_sum_256(float val, float* sh)
{
    const int lane = threadIdx.x & 31;
    const int w    = threadIdx.x >> 5;
#pragma unroll
    for (int o = 16; o > 0; o >>= 1) val += __shfl_xor_sync(0xffffffffu, val, o);
    if (lane == 0) sh[w] = val;
    __syncthreads();
    if (w == 0) {
        float t = (lane < 8) ? sh[lane] : 0.f;
#pragma unroll
        for (int o = 4; o > 0; o >>= 1) t += __shfl_xor_sync(0xffffffffu, t, o);
        if (lane == 0) sh[0] = t;
    }
    __syncthreads();
    const float r = sh[0];
    __syncthreads();
    return r;
}

__global__ __launch_bounds__(256) void k_ln(const float* __restrict__ x,
                                            const float* __restrict__ gamma,
                                            const float* __restrict__ beta,
                                            float* __restrict__ out)
{
    __shared__ float sh[8];
    const int srow = blockIdx.x;
    const float* orow = g_out + (size_t)srow * EM;
    const float* xrow = x + (size_t)srow * EM;

    float v[4];
    float sum = 0.f;
#pragma unroll
    for (int i = 0; i < 4; i++) {
        const int c = threadIdx.x + i * 256;
        v[i] = orow[c] + xrow[c];
        sum += v[i];
    }
    const float mean = block_sum_256(sum, sh) * (1.f / EM);

    float var = 0.f;
#pragma unroll
    for (int i = 0; i < 4; i++) {
        const float d = v[i] - mean;
        var += d * d;
    }
    const float rstd = rsqrtf(block_sum_256(var, sh) * (1.f / EM) + 1e-5f);

#pragma unroll
    for (int i = 0; i < 4; i++) {
        const int c = threadIdx.x + i * 256;
        out[(size_t)srow * EM + c] = (v[i] - mean) * rstd * gamma[c] + beta[c];
    }
}

// ---------------- launch ----------------
extern "C" void kernel_launch(void* const* d_in, const int* in_sizes, int n_in,
                              void* d_out, int out_size)
{
    const float* x     = (const float*)d_in[0];
    const float* Wk    = (const float*)d_in[1];
    const float* Wq    = (const float*)d_in[2];
    const float* Wv    = (const float*)d_in[3];
    const float* hWk   = (const float*)d_in[4];
    const float* hbk   = (const float*)d_in[5];
    const float* hWv   = (const float*)d_in[6];
    const float* hbv   = (const float*)d_in[7];
    const float* hWq   = (const float*)d_in[8];
    const float* hbq   = (const float*)d_in[9];
    const float* Wo    = (const float*)d_in[10];
    const float* bo    = (const float*)d_in[11];
    const float* gamma = (const float*)d_in[12];
    const float* beta  = (const float*)d_in[13];
    float* out = (float*)d_out;

    k_splitW<<<EM, 128>>>(Wo);
    k_proj<<<dim3(1, SQ / 64, 3), 128>>>(x, Wk, Wq, Wv);
    k_headlin<<<dim3(1, SQ / 64, 48), 128>>>(hWk, hbk, hWv, hbv, hWq, hbq);
    k_transpose<<<dim3(SQ / 32, DM / 32, NH), dim3(32, 8)>>>();
    k_attn<<<dim3(SQ / 64, NH), 128>>>();
    k_outproj<<<dim3(EM / 128, SQ / 128), 256>>>(bo);
    k_ln<<<SQ, 256>>>(x, gamma, beta, out);
}

// round 7
// speedup vs baseline: 2.6560x; 1.2364x over previous
#include <cuda_runtime.h>
#include <math.h>

#define SQ 2048
#define EM 1024
#define DM 64
#define NH 16

// ---------------- scratch: packed bf16x2 hi/lo pair arrays ----------------
__device__ __align__(16) unsigned g_pKh[SQ * 32], g_pKl[SQ * 32];
__device__ __align__(16) unsigned g_pQh[SQ * 32], g_pQl[SQ * 32];
__device__ __align__(16) unsigned g_pVh[SQ * 32], g_pVl[SQ * 32];
__device__ __align__(16) unsigned g_hKh[NH * SQ * 32], g_hKl[NH * SQ * 32];
__device__ __align__(16) unsigned g_hQh[NH * SQ * 32], g_hQl[NH * SQ * 32];
__device__ __align__(16) float    g_Vh[NH * SQ * DM];
__device__ __align__(16) unsigned g_tVh[NH * DM * (SQ / 2)], g_tVl[NH * DM * (SQ / 2)];
__device__ __align__(16) unsigned g_ch[SQ * (EM / 2)], g_cl[SQ * (EM / 2)];
__device__ __align__(16) unsigned g_Woh[EM * (EM / 2)], g_Wol[EM * (EM / 2)];
__device__ __align__(16) float    g_out[SQ * EM];

// ---------------- bf16 split helpers ----------------
__device__ __forceinline__ unsigned pk2(float x, float y) {
    unsigned r;
    asm("cvt.rn.bf16x2.f32 %0, %1, %2;" : "=r"(r) : "f"(y), "f"(x));
    return r;
}

__device__ __forceinline__ void sp2(float x, float y, unsigned& hi, unsigned& lo) {
    unsigned ux = __float_as_uint(x), uy = __float_as_uint(y);
    hi = __byte_perm(ux, uy, 0x7632);
    float rx = x - __uint_as_float(ux & 0xffff0000u);
    float ry = y - __uint_as_float(uy & 0xffff0000u);
    lo = pk2(rx, ry);
}

__device__ __forceinline__ void mma_bf16(float* d, const unsigned* a, const unsigned* b) {
    asm volatile(
        "mma.sync.aligned.m16n8k16.row.col.f32.bf16.bf16.f32 "
        "{%0,%1,%2,%3},{%4,%5,%6,%7},{%8,%9},{%0,%1,%2,%3};"
        : "+f"(d[0]), "+f"(d[1]), "+f"(d[2]), "+f"(d[3])
        : "r"(a[0]), "r"(a[1]), "r"(a[2]), "r"(a[3]), "r"(b[0]), "r"(b[1]));
}

__device__ __forceinline__ void cp16(unsigned* smem_dst, const void* gsrc) {
    unsigned daddr = (unsigned)__cvta_generic_to_shared(smem_dst);
    asm volatile("cp.async.cg.shared.global [%0], [%1], 16;" :: "r"(daddr), "l"(gsrc));
}

// ======== split-bf16 3-term GEMM: C = A @ B^T (+bias), BK=32 ========
#define SK 20

template <int BM, int BN, int WM, int WN, bool ASPLIT, bool BSPLIT, bool OUTPAIR>
__device__ __forceinline__ void gemm3x(
    const float* A, const unsigned* Aph, const unsigned* Apl, int lda,
    const float* B, const unsigned* Bph, const unsigned* Bpl, int ldb,
    const float* bias,
    float* C, unsigned* Cph, unsigned* Cpl, int ldc,
    float oscale, int Kd, int m0, int n0,
    unsigned* Ah, unsigned* Al, unsigned* Bh, unsigned* Bl)
{
    constexpr int NT = WM * WN * 32;
    constexpr int MF = BM / (WM * 16);
    constexpr int NF = BN / (WN * 8);
    const int tid  = threadIdx.x;
    const int lane = tid & 31;
    const int warp = tid >> 5;
    const int wm   = warp % WM;
    const int wn   = warp / WM;
    const int g    = lane >> 2;
    const int lam  = lane & 3;

    float acc[MF][NF][4];
#pragma unroll
    for (int mf = 0; mf < MF; mf++)
#pragma unroll
        for (int nf = 0; nf < NF; nf++)
#pragma unroll
            for (int i = 0; i < 4; i++) acc[mf][nf][i] = 0.f;

    for (int k0 = 0; k0 < Kd; k0 += 32) {
        __syncthreads();
        if (ASPLIT) {
#pragma unroll
            for (int e = tid; e < BM * 4; e += NT) {
                int r = e >> 2, c = e & 3;
                size_t off = (size_t)(m0 + r) * lda + (k0 >> 1) + c * 4;
                *reinterpret_cast<uint4*>(Ah + r * SK + c * 4) = *reinterpret_cast<const uint4*>(Aph + off);
                *reinterpret_cast<uint4*>(Al + r * SK + c * 4) = *reinterpret_cast<const uint4*>(Apl + off);
            }
        } else {
#pragma unroll
            for (int e = tid; e < BM * 8; e += NT) {
                int r = e >> 3, c4 = e & 7;
                float4 v = *reinterpret_cast<const float4*>(A + (size_t)(m0 + r) * lda + k0 + c4 * 4);
                sp2(v.x, v.y, Ah[r * SK + c4 * 2 + 0], Al[r * SK + c4 * 2 + 0]);
                sp2(v.z, v.w, Ah[r * SK + c4 * 2 + 1], Al[r * SK + c4 * 2 + 1]);
            }
        }
        if (BSPLIT) {
#pragma unroll
            for (int e = tid; e < BN * 4; e += NT) {
                int r = e >> 2, c = e & 3;
                size_t off = (size_t)(n0 + r) * ldb + (k0 >> 1) + c * 4;
                *reinterpret_cast<uint4*>(Bh + r * SK + c * 4) = *reinterpret_cast<const uint4*>(Bph + off);
                *reinterpret_cast<uint4*>(Bl + r * SK + c * 4) = *reinterpret_cast<const uint4*>(Bpl + off);
            }
        } else {
#pragma unroll
            for (int e = tid; e < BN * 8; e += NT) {
                int r = e >> 3, c4 = e & 7;
                float4 v = *reinterpret_cast<const float4*>(B + (size_t)(n0 + r) * ldb + k0 + c4 * 4);
                sp2(v.x, v.y, Bh[r * SK + c4 * 2 + 0], Bl[r * SK + c4 * 2 + 0]);
                sp2(v.z, v.w, Bh[r * SK + c4 * 2 + 1], Bl[r * SK + c4 * 2 + 1]);
            }
        }
        __syncthreads();

#pragma unroll
        for (int kc = 0; kc < 2; kc++) {
            unsigned ah[MF][4], al[MF][4];
#pragma unroll
            for (int mf = 0; mf < MF; mf++) {
                const int r = wm * (MF * 16) + mf * 16 + g;
                ah[mf][0] = Ah[r * SK + kc * 8 + lam];
                ah[mf][1] = Ah[(r + 8) * SK + kc * 8 + lam];
                ah[mf][2] = Ah[r * SK + kc * 8 + lam + 4];
                ah[mf][3] = Ah[(r + 8) * SK + kc * 8 + lam + 4];
                al[mf][0] = Al[r * SK + kc * 8 + lam];
                al[mf][1] = Al[(r + 8) * SK + kc * 8 + lam];
                al[mf][2] = Al[r * SK + kc * 8 + lam + 4];
                al[mf][3] = Al[(r + 8) * SK + kc * 8 + lam + 4];
            }
#pragma unroll
            for (int nf = 0; nf < NF; nf++) {
                const int rb = wn * (NF * 8) + nf * 8 + g;
                unsigned bh[2], bl[2];
                bh[0] = Bh[rb * SK + kc * 8 + lam];
                bh[1] = Bh[rb * SK + kc * 8 + lam + 4];
                bl[0] = Bl[rb * SK + kc * 8 + lam];
                bl[1] = Bl[rb * SK + kc * 8 + lam + 4];
#pragma unroll
                for (int mf = 0; mf < MF; mf++) {
                    mma_bf16(acc[mf][nf], ah[mf], bl);
                    mma_bf16(acc[mf][nf], al[mf], bh);
                    mma_bf16(acc[mf][nf], ah[mf], bh);
                }
            }
        }
    }

#pragma unroll
    for (int mf = 0; mf < MF; mf++) {
        const int row = m0 + wm * (MF * 16) + mf * 16 + g;
#pragma unroll
        for (int nf = 0; nf < NF; nf++) {
            if (OUTPAIR) {
                const int pc = (n0 >> 1) + wn * (NF * 4) + nf * 4 + lam;
                float b0 = bias ? bias[2 * pc] : 0.f;
                float b1 = bias ? bias[2 * pc + 1] : 0.f;
                unsigned hi, lo;
                sp2((acc[mf][nf][0] + b0) * oscale, (acc[mf][nf][1] + b1) * oscale, hi, lo);
                Cph[(size_t)row * ldc + pc] = hi;
                Cpl[(size_t)row * ldc + pc] = lo;
                sp2((acc[mf][nf][2] + b0) * oscale, (acc[mf][nf][3] + b1) * oscale, hi, lo);
                Cph[(size_t)(row + 8) * ldc + pc] = hi;
                Cpl[(size_t)(row + 8) * ldc + pc] = lo;
            } else {
                const int col = n0 + wn * (NF * 8) + nf * 8 + 2 * lam;
                float b0 = bias ? bias[col] : 0.f;
                float b1 = bias ? bias[col + 1] : 0.f;
                float2 v0 = make_float2(acc[mf][nf][0] + b0, acc[mf][nf][1] + b1);
                float2 v1 = make_float2(acc[mf][nf][2] + b0, acc[mf][nf][3] + b1);
                *reinterpret_cast<float2*>(C + (size_t)row * ldc + col) = v0;
                *reinterpret_cast<float2*>(C + (size_t)(row + 8) * ldc + col) = v1;
            }
        }
    }
}

// ---------------- kernel 0: pre-split Wo ----------------
__global__ __launch_bounds__(128) void k_splitW(const float* __restrict__ Wo)
{
    const int r = blockIdx.x;
#pragma unroll
    for (int i = 0; i < 2; i++) {
        int c4 = threadIdx.x + i * 128;
        float4 v = *reinterpret_cast<const float4*>(Wo + (size_t)r * EM + c4 * 4);
        unsigned h0, l0, h1, l1;
        sp2(v.x, v.y, h0, l0);
        sp2(v.z, v.w, h1, l1);
        g_Woh[(size_t)r * 512 + c4 * 2 + 0] = h0;
        g_Wol[(size_t)r * 512 + c4 * 2 + 0] = l0;
        g_Woh[(size_t)r * 512 + c4 * 2 + 1] = h1;
        g_Wol[(size_t)r * 512 + c4 * 2 + 1] = l1;
    }
}

// ---------------- kernel 1: shared projections -> split pairs ----------------
__global__ __launch_bounds__(128) void k_proj(const float* __restrict__ x,
                                              const float* __restrict__ Wk,
                                              const float* __restrict__ Wq,
                                              const float* __restrict__ Wv)
{
    __shared__ unsigned Ah[64 * SK], Al[64 * SK], Bh[64 * SK], Bl[64 * SK];
    const float* W;
    unsigned *Ch, *Cl;
    if (blockIdx.z == 0)      { W = Wk; Ch = g_pKh; Cl = g_pKl; }
    else if (blockIdx.z == 1) { W = Wq; Ch = g_pQh; Cl = g_pQl; }
    else                      { W = Wv; Ch = g_pVh; Cl = g_pVl; }
    gemm3x<64, 64, 2, 2, false, false, true>(
        x, nullptr, nullptr, EM, W, nullptr, nullptr, EM, nullptr,
        nullptr, Ch, Cl, 32, 1.f, EM, blockIdx.y * 64, 0, Ah, Al, Bh, Bl);
}

// ---------------- kernel 2: per-head linears ----------------
__global__ __launch_bounds__(128) void k_headlin(const float* __restrict__ hWk,
                                                 const float* __restrict__ hbk,
                                                 const float* __restrict__ hWv,
                                                 const float* __restrict__ hbv,
                                                 const float* __restrict__ hWq,
                                                 const float* __restrict__ hbq)
{
    __shared__ unsigned Ah[64 * SK], Al[64 * SK], Bh[64 * SK], Bl[64 * SK];
    const int z = blockIdx.z;
    const int t = z >> 4;
    const int h = z & 15;
    const int m0 = blockIdx.y * 64;
    if (t == 0) {
        gemm3x<64, 64, 2, 2, true, false, true>(
            nullptr, g_pKh, g_pKl, 32, hWk + h * DM * DM, nullptr, nullptr, DM, hbk + h * DM,
            nullptr, g_hKh + (size_t)h * SQ * 32, g_hKl + (size_t)h * SQ * 32, 32,
            1.f, DM, m0, 0, Ah, Al, Bh, Bl);
    } else if (t == 2) {
        gemm3x<64, 64, 2, 2, true, false, true>(
            nullptr, g_pQh, g_pQl, 32, hWq + h * DM * DM, nullptr, nullptr, DM, hbq + h * DM,
            nullptr, g_hQh + (size_t)h * SQ * 32, g_hQl + (size_t)h * SQ * 32, 32,
            0.125f, DM, m0, 0, Ah, Al, Bh, Bl);
    } else {
        gemm3x<64, 64, 2, 2, true, false, false>(
            nullptr, g_pVh, g_pVl, 32, hWv + h * DM * DM, nullptr, nullptr, DM, hbv + h * DM,
            g_Vh + (size_t)h * SQ * DM, nullptr, nullptr, DM,
            1.f, DM, m0, 0, Ah, Al, Bh, Bl);
    }
}

// ---------------- kernel 2b: transpose Vh -> split Vt pairs [h][d][s/2] -------
__global__ void k_transpose()
{
    __shared__ float t[32][33];
    const int h  = blockIdx.z;
    const int s0 = blockIdx.x * 32;
    const int d0 = blockIdx.y * 32;
    const int tx = threadIdx.x, ty = threadIdx.y;
    const float* src = g_Vh + (size_t)h * SQ * DM;
#pragma unroll
    for (int i = 0; i < 4; i++)
        t[ty + i * 8][tx] = src[(size_t)(s0 + ty + i * 8) * DM + d0 + tx];
    __syncthreads();
    const int tid = ty * 32 + tx;
#pragma unroll
    for (int i = 0; i < 2; i++) {
        int o  = tid + i * 256;
        int dl = o >> 4, p = o & 15;
        unsigned hi, lo;
        sp2(t[2 * p][dl], t[2 * p + 1][dl], hi, lo);
        size_t idx = ((size_t)h * DM + d0 + dl) * (SQ / 2) + (s0 >> 1) + p;
        g_tVh[idx] = hi;
        g_tVl[idx] = lo;
    }
}

// ---------- kernel 3: flash attention, 256 thr / 128 q-rows, cp.async 2-stage ----
#define AS 36                 // smem row stride (words): 32 pairs/row, conflict-free
#define TW (64 * AS)          // words per tile array
#define STAGE_W (4 * TW)      // words per stage (Kh,Kl,Vh,Vl)

__global__ __launch_bounds__(256, 1) void k_attn()
{
    extern __shared__ unsigned sm[];
    const int h    = blockIdx.y;
    const int tid  = threadIdx.x;
    const int lane = tid & 31;
    const int warp = tid >> 5;
    const int g    = lane >> 2;
    const int lam  = lane & 3;
    const int q0   = blockIdx.x * 128 + warp * 16;

    const unsigned* Qh_ = g_hQh + (size_t)h * SQ * 32;
    const unsigned* Ql_ = g_hQl + (size_t)h * SQ * 32;
    const unsigned* Kh_ = g_hKh + (size_t)h * SQ * 32;
    const unsigned* Kl_ = g_hKl + (size_t)h * SQ * 32;
    const unsigned* Vh_ = g_tVh + (size_t)h * DM * (SQ / 2);
    const unsigned* Vl_ = g_tVl + (size_t)h * DM * (SQ / 2);

    // Q fragments (pre-split, pre-scaled)
    unsigned qh[4][4], ql[4][4];
#pragma unroll
    for (int kc = 0; kc < 4; kc++) {
        qh[kc][0] = Qh_[(size_t)(q0 + g) * 32 + kc * 8 + lam];
        qh[kc][1] = Qh_[(size_t)(q0 + g + 8) * 32 + kc * 8 + lam];
        qh[kc][2] = Qh_[(size_t)(q0 + g) * 32 + kc * 8 + 4 + lam];
        qh[kc][3] = Qh_[(size_t)(q0 + g + 8) * 32 + kc * 8 + 4 + lam];
        ql[kc][0] = Ql_[(size_t)(q0 + g) * 32 + kc * 8 + lam];
        ql[kc][1] = Ql_[(size_t)(q0 + g + 8) * 32 + kc * 8 + lam];
        ql[kc][2] = Ql_[(size_t)(q0 + g) * 32 + kc * 8 + 4 + lam];
        ql[kc][3] = Ql_[(size_t)(q0 + g + 8) * 32 + kc * 8 + 4 + lam];
    }

    float o[8][4];
#pragma unroll
    for (int nf = 0; nf < 8; nf++)
#pragma unroll
        for (int i = 0; i < 4; i++) o[nf][i] = 0.f;
    float m0r = -1e30f, m1r = -1e30f, l0 = 0.f, l1 = 0.f;

    // async fill of one stage (64-key tile): 2048 uint4 across 256 threads
    auto fill = [&](int stage, int t0) {
        unsigned* bKh = sm + stage * STAGE_W;
        unsigned* bKl = bKh + TW;
        unsigned* bVh = bKl + TW;
        unsigned* bVl = bVh + TW;
#pragma unroll
        for (int i = 0; i < 2; i++) {
            int e = tid + i * 256;
            int r = e >> 3, c = e & 7;
            size_t ko = (size_t)(t0 + r) * 32 + c * 4;
            cp16(bKh + r * AS + c * 4, Kh_ + ko);
            cp16(bKl + r * AS + c * 4, Kl_ + ko);
            size_t vo = (size_t)r * (SQ / 2) + (t0 >> 1) + c * 4;
            cp16(bVh + r * AS + c * 4, Vh_ + vo);
            cp16(bVl + r * AS + c * 4, Vl_ + vo);
        }
        asm volatile("cp.async.commit_group;");
    };

    fill(0, 0);

    for (int it = 0; it < SQ / 64; it++) {
        const int cur = it & 1;
        if (it + 1 < SQ / 64) {
            fill(cur ^ 1, (it + 1) * 64);
            asm volatile("cp.async.wait_group 1;");
        } else {
            asm volatile("cp.async.wait_group 0;");
        }
        __syncthreads();

        const unsigned* sKh = sm + cur * STAGE_W;
        const unsigned* sKl = sKh + TW;
        const unsigned* sVh = sKl + TW;
        const unsigned* sVl = sVh + TW;

        // S = Q K^T, 3-term (m16 x n64 per warp, k=64)
        float s[8][4];
#pragma unroll
        for (int nf = 0; nf < 8; nf++) {
            s[nf][0] = s[nf][1] = s[nf][2] = s[nf][3] = 0.f;
            const int rb = nf * 8 + g;
#pragma unroll
            for (int kc = 0; kc < 4; kc++) {
                unsigned bh[2], bl[2];
                bh[0] = sKh[rb * AS + kc * 8 + lam];
                bh[1] = sKh[rb * AS + kc * 8 + 4 + lam];
                bl[0] = sKl[rb * AS + kc * 8 + lam];
                bl[1] = sKl[rb * AS + kc * 8 + 4 + lam];
                mma_bf16(s[nf], qh[kc], bl);
                mma_bf16(s[nf], ql[kc], bh);
                mma_bf16(s[nf], qh[kc], bh);
            }
        }

        // online softmax
        float mx0 = m0r, mx1 = m1r;
#pragma unroll
        for (int nf = 0; nf < 8; nf++) {
            mx0 = fmaxf(mx0, fmaxf(s[nf][0], s[nf][1]));
            mx1 = fmaxf(mx1, fmaxf(s[nf][2], s[nf][3]));
        }
        mx0 = fmaxf(mx0, __shfl_xor_sync(0xffffffffu, mx0, 1));
        mx0 = fmaxf(mx0, __shfl_xor_sync(0xffffffffu, mx0, 2));
        mx1 = fmaxf(mx1, __shfl_xor_sync(0xffffffffu, mx1, 1));
        mx1 = fmaxf(mx1, __shfl_xor_sync(0xffffffffu, mx1, 2));

        const float c0 = __expf(m0r - mx0);
        const float c1 = __expf(m1r - mx1);
        m0r = mx0; m1r = mx1;

        float ls0 = 0.f, ls1 = 0.f;
#pragma unroll
        for (int nf = 0; nf < 8; nf++) {
            s[nf][0] = __expf(s[nf][0] - mx0);
            s[nf][1] = __expf(s[nf][1] - mx0);
            s[nf][2] = __expf(s[nf][2] - mx1);
            s[nf][3] = __expf(s[nf][3] - mx1);
            ls0 += s[nf][0] + s[nf][1];
            ls1 += s[nf][2] + s[nf][3];
        }
        ls0 += __shfl_xor_sync(0xffffffffu, ls0, 1);
        ls0 += __shfl_xor_sync(0xffffffffu, ls0, 2);
        ls1 += __shfl_xor_sync(0xffffffffu, ls1, 1);
        ls1 += __shfl_xor_sync(0xffffffffu, ls1, 2);
        l0 = l0 * c0 + ls0;
        l1 = l1 * c1 + ls1;
#pragma unroll
        for (int nf = 0; nf < 8; nf++) {
            o[nf][0] *= c0; o[nf][1] *= c0;
            o[nf][2] *= c1; o[nf][3] *= c1;
        }

        // P: C-layout == A-layout -> pack directly
        unsigned ph[4][4], pl[4][4];
#pragma unroll
        for (int kc = 0; kc < 4; kc++) {
            sp2(s[2 * kc][0],     s[2 * kc][1],     ph[kc][0], pl[kc][0]);
            sp2(s[2 * kc][2],     s[2 * kc][3],     ph[kc][1], pl[kc][1]);
            sp2(s[2 * kc + 1][0], s[2 * kc + 1][1], ph[kc][2], pl[kc][2]);
            sp2(s[2 * kc + 1][2], s[2 * kc + 1][3], ph[kc][3], pl[kc][3]);
        }

        // O += P V, 3-term
#pragma unroll
        for (int nf = 0; nf < 8; nf++) {
            const int rb = nf * 8 + g;
#pragma unroll
            for (int kc = 0; kc < 4; kc++) {
                unsigned bh[2], bl[2];
                bh[0] = sVh[rb * AS + kc * 8 + lam];
                bh[1] = sVh[rb * AS + kc * 8 + 4 + lam];
                bl[0] = sVl[rb * AS + kc * 8 + lam];
                bl[1] = sVl[rb * AS + kc * 8 + 4 + lam];
                mma_bf16(o[nf], ph[kc], bl);
                mma_bf16(o[nf], pl[kc], bh);
                mma_bf16(o[nf], ph[kc], bh);
            }
        }
        __syncthreads();
    }

    // epilogue: write cat as split pairs
    const float inv0 = 1.f / l0;
    const float inv1 = 1.f / l1;
#pragma unroll
    for (int nf = 0; nf < 8; nf++) {
        const int pc = h * 32 + nf * 4 + lam;
        unsigned hi, lo;
        sp2(o[nf][0] * inv0, o[nf][1] * inv0, hi, lo);
        g_ch[(size_t)(q0 + g) * 512 + pc] = hi;
        g_cl[(size_t)(q0 + g) * 512 + pc] = lo;
        sp2(o[nf][2] * inv1, o[nf][3] * inv1, hi, lo);
        g_ch[(size_t)(q0 + g + 8) * 512 + pc] = hi;
        g_cl[(size_t)(q0 + g + 8) * 512 + pc] = lo;
    }
}

// ---------------- kernel 4: out-proj (pre-split A and B) ----------------
__global__ __launch_bounds__(256) void k_outproj(const float* __restrict__ bo)
{
    __shared__ unsigned Ah[128 * SK], Al[128 * SK], Bh[128 * SK], Bl[128 * SK];
    gemm3x<128, 128, 4, 2, true, true, false>(
        nullptr, g_ch, g_cl, 512, nullptr, g_Woh, g_Wol, 512, bo,
        g_out, nullptr, nullptr, EM, 1.f, EM,
        blockIdx.y * 128, blockIdx.x * 128, Ah, Al, Bh, Bl);
}

// ---------------- kernel 5: residual + LayerNorm ----------------
__device__ __forceinline__ float block_sum_256(float val, float* sh)
{
    const int lane = threadIdx.x & 31;
    const int w    = threadIdx.x >> 5;
#pragma unroll
    for (int o = 16; o > 0; o >>= 1) val += __shfl_xor_sync(0xffffffffu, val, o);
    if (lane == 0) sh[w] = val;
    __syncthreads();
    if (w == 0) {
        float t = (lane < 8) ? sh[lane] : 0.f;
#pragma unroll
        for (int o = 4; o > 0; o >>= 1) t += __shfl_xor_sync(0xffffffffu, t, o);
        if (lane == 0) sh[0] = t;
    }
    __syncthreads();
    const float r = sh[0];
    __syncthreads();
    return r;
}

__global__ __launch_bounds__(256) void k_ln(const float* __restrict__ x,
                                            const float* __restrict__ gamma,
                                            const float* __restrict__ beta,
                                            float* __restrict__ out)
{
    __shared__ float sh[8];
    const int srow = blockIdx.x;
    const float* orow = g_out + (size_t)srow * EM;
    const float* xrow = x + (size_t)srow * EM;

    float v[4];
    float sum = 0.f;
#pragma unroll
    for (int i = 0; i < 4; i++) {
        const int c = threadIdx.x + i * 256;
        v[i] = orow[c] + xrow[c];
        sum += v[i];
    }
    const float mean = block_sum_256(sum, sh) * (1.f / EM);

    float var = 0.f;
#pragma unroll
    for (int i = 0; i < 4; i++) {
        const float d = v[i] - mean;
        var += d * d;
    }
    const float rstd = rsqrtf(block_sum_256(var, sh) * (1.f / EM) + 1e-5f);

#pragma unroll
    for (int i = 0; i < 4; i++) {
        const int c = threadIdx.x + i * 256;
        out[(size_t)srow * EM + c] = (v[i] - mean) * rstd * gamma[c] + beta[c];
    }
}

// ---------------- launch ----------------
extern "C" void kernel_launch(void* const* d_in, const int* in_sizes, int n_in,
                              void* d_out, int out_size)
{
    const float* x     = (const float*)d_in[0];
    const float* Wk    = (const float*)d_in[1];
    const float* Wq    = (const float*)d_in[2];
    const float* Wv    = (const float*)d_in[3];
    const float* hWk   = (const float*)d_in[4];
    const float* hbk   = (const float*)d_in[5];
    const float* hWv   = (const float*)d_in[6];
    const float* hbv   = (const float*)d_in[7];
    const float* hWq   = (const float*)d_in[8];
    const float* hbq   = (const float*)d_in[9];
    const float* Wo    = (const float*)d_in[10];
    const float* bo    = (const float*)d_in[11];
    const float* gamma = (const float*)d_in[12];
    const float* beta  = (const float*)d_in[13];
    float* out = (float*)d_out;

    const int attn_smem = 2 * STAGE_W * 4;   // bytes: 2 stages x 4 arrays x 64*AS words
    cudaFuncSetAttribute(k_attn, cudaFuncAttributeMaxDynamicSharedMemorySize, attn_smem);

    k_splitW<<<EM, 128>>>(Wo);
    k_proj<<<dim3(1, SQ / 64, 3), 128>>>(x, Wk, Wq, Wv);
    k_headlin<<<dim3(1, SQ / 64, 48), 128>>>(hWk, hbk, hWv, hbv, hWq, hbq);
    k_transpose<<<dim3(SQ / 32, DM / 32, NH), dim3(32, 8)>>>();
    k_attn<<<dim3(SQ / 128, NH), 256, attn_smem>>>();
    k_outproj<<<dim3(EM / 128, SQ / 128), 256>>>(bo);
    k_ln<<<SQ, 256>>>(x, gamma, beta, out);
}